// round 3
// baseline (speedup 1.0000x reference)
#include <cuda_runtime.h>
#include <math.h>

#define NMAX 1024

static __device__ __forceinline__ float finf() { return __int_as_float(0x7f800000); }

// Sorted (render-ready) SoA scratch
__device__ float4 g_A[NMAX]; // mx, my, conA, conB
__device__ float4 g_B[NMAX]; // conC, op, colR, colG
__device__ float2 g_C[NMAX]; // colB, depth
// Unsorted scratch
__device__ float4 u_A[NMAX];
__device__ float4 u_B[NMAX];
__device__ float2 u_C[NMAX];

__global__ __launch_bounds__(NMAX) void preprocess_sort_kernel(
    const float* __restrict__ means3d,   // [N,3]
    const float* __restrict__ quats,     // [N,4]
    const float* __restrict__ scales,    // [N,3]
    const float* __restrict__ opac,      // [N]
    const float* __restrict__ sh,        // [N,4,3]
    const float* __restrict__ c2w,       // [4,4]
    const float* __restrict__ Ks,        // [3,3]
    int N)
{
    const float SH_C0 = 0.28209479177387814f;
    const float SH_C1 = 0.4886025119029199f;
    const float NEARP = 0.01f;
    const float FARP  = 1e10f;
    const float LOWPASS = 0.3f;

    __shared__ float skey[NMAX];
    __shared__ int   sidx[NMAX];

    int i = threadIdx.x;
    float key = finf();

    if (i < N) {
        // viewmat = inv(camtoworld) (rigid): Rw = camR^T, tw = -Rw * camt
        float Rw[3][3];
        #pragma unroll
        for (int r = 0; r < 3; r++)
            #pragma unroll
            for (int c = 0; c < 3; c++)
                Rw[r][c] = c2w[c * 4 + r];
        float ct0 = c2w[3], ct1 = c2w[7], ct2 = c2w[11];
        float tw[3];
        #pragma unroll
        for (int r = 0; r < 3; r++)
            tw[r] = -(Rw[r][0] * ct0 + Rw[r][1] * ct1 + Rw[r][2] * ct2);

        float fx = Ks[0], cx = Ks[2], fy = Ks[4], cy = Ks[5];

        float m0 = means3d[i * 3 + 0], m1 = means3d[i * 3 + 1], m2 = means3d[i * 3 + 2];
        float x = Rw[0][0] * m0 + Rw[0][1] * m1 + Rw[0][2] * m2 + tw[0];
        float y = Rw[1][0] * m0 + Rw[1][1] * m1 + Rw[1][2] * m2 + tw[1];
        float z = Rw[2][0] * m0 + Rw[2][1] * m1 + Rw[2][2] * m2 + tw[2];

        bool valid = (z > NEARP) && (z < FARP);
        float zs = valid ? z : 1.0f;
        float m2x = fx * x / zs + cx;
        float m2y = fy * y / zs + cy;

        // quat -> rotmat
        float qw = quats[i * 4 + 0], qx = quats[i * 4 + 1], qy = quats[i * 4 + 2], qz = quats[i * 4 + 3];
        float qn = rsqrtf(qw * qw + qx * qx + qy * qy + qz * qz);
        qw *= qn; qx *= qn; qy *= qn; qz *= qn;
        float Rg[3][3];
        Rg[0][0] = 1.f - 2.f * (qy * qy + qz * qz);
        Rg[0][1] = 2.f * (qx * qy - qw * qz);
        Rg[0][2] = 2.f * (qx * qz + qw * qy);
        Rg[1][0] = 2.f * (qx * qy + qw * qz);
        Rg[1][1] = 1.f - 2.f * (qx * qx + qz * qz);
        Rg[1][2] = 2.f * (qy * qz - qw * qx);
        Rg[2][0] = 2.f * (qx * qz - qw * qy);
        Rg[2][1] = 2.f * (qy * qz + qw * qx);
        Rg[2][2] = 1.f - 2.f * (qx * qx + qy * qy);

        float s0 = scales[i * 3 + 0], s1 = scales[i * 3 + 1], s2v = scales[i * 3 + 2];
        float sq[3] = { s0 * s0, s1 * s1, s2v * s2v };

        // cov3d = (Rg * diag(s)) (Rg * diag(s))^T
        float cov3[3][3];
        #pragma unroll
        for (int r = 0; r < 3; r++)
            #pragma unroll
            for (int c = 0; c < 3; c++)
                cov3[r][c] = Rg[r][0] * Rg[c][0] * sq[0]
                           + Rg[r][1] * Rg[c][1] * sq[1]
                           + Rg[r][2] * Rg[c][2] * sq[2];

        // cov_cam = Rw cov3 Rw^T
        float Vc[3][3];
        #pragma unroll
        for (int r = 0; r < 3; r++)
            #pragma unroll
            for (int c = 0; c < 3; c++)
                Vc[r][c] = Rw[r][0] * cov3[0][c] + Rw[r][1] * cov3[1][c] + Rw[r][2] * cov3[2][c];
        float cc[3][3];
        #pragma unroll
        for (int r = 0; r < 3; r++)
            #pragma unroll
            for (int c = 0; c < 3; c++)
                cc[r][c] = Vc[r][0] * Rw[c][0] + Vc[r][1] * Rw[c][1] + Vc[r][2] * Rw[c][2];

        // J (2x3), cov2d = J cov_cam J^T
        float j00 = fx / zs, j02 = -fx * x / (zs * zs);
        float j11 = fy / zs, j12 = -fy * y / (zs * zs);
        float a = j00 * (cc[0][0] * j00 + cc[0][2] * j02)
                + j02 * (cc[2][0] * j00 + cc[2][2] * j02);
        float b = j00 * (cc[0][1] * j11 + cc[0][2] * j12)
                + j02 * (cc[2][1] * j11 + cc[2][2] * j12);
        float c = j11 * (cc[1][1] * j11 + cc[1][2] * j12)
                + j12 * (cc[2][1] * j11 + cc[2][2] * j12);
        a += LOWPASS;
        c += LOWPASS;
        float det = a * c - b * b;
        valid = valid && (det > 0.f);
        float dets = (det > 0.f) ? det : 1.0f;
        float conA = c / dets, conB = -b / dets, conC = a / dets;

        // SH degree-1 color
        float dx3 = m0 - ct0, dy3 = m1 - ct1, dz3 = m2 - ct2;
        float dn = sqrtf(dx3 * dx3 + dy3 * dy3 + dz3 * dz3);
        dn = fmaxf(dn, 1e-8f);
        float dxn = dx3 / dn, dyn = dy3 / dn, dzn = dz3 / dn;
        float col[3];
        #pragma unroll
        for (int ch = 0; ch < 3; ch++) {
            float v = SH_C0 * sh[i * 12 + ch]
                    - SH_C1 * dyn * sh[i * 12 + 3 + ch]
                    + SH_C1 * dzn * sh[i * 12 + 6 + ch]
                    - SH_C1 * dxn * sh[i * 12 + 9 + ch];
            col[ch] = fmaxf(v + 0.5f, 0.0f);
        }

        float op = 1.0f / (1.0f + __expf(-opac[i]));
        op = valid ? op : 0.0f;

        u_A[i] = make_float4(m2x, m2y, conA, conB);
        u_B[i] = make_float4(conC, op, col[0], col[1]);
        u_C[i] = make_float2(col[2], z);

        key = valid ? z : finf();
    }

    skey[i] = key;
    sidx[i] = i;
    __syncthreads();

    // Bitonic sort, ascending by key
    for (int k = 2; k <= NMAX; k <<= 1) {
        for (int j = k >> 1; j > 0; j >>= 1) {
            int p = i ^ j;
            if (p > i) {
                bool up = ((i & k) == 0);
                float ka = skey[i], kb = skey[p];
                bool swap = up ? (ka > kb) : (ka < kb);
                if (swap) {
                    int ia = sidx[i];
                    skey[i] = kb; skey[p] = ka;
                    sidx[i] = sidx[p]; sidx[p] = ia;
                }
            }
            __syncthreads();
        }
    }

    // Gather sorted SoA
    if (i < N) {
        int s = sidx[i];
        if (s < N) {
            g_A[i] = u_A[s];
            g_B[i] = u_B[s];
            g_C[i] = u_C[s];
        } else {
            g_A[i] = make_float4(0.f, 0.f, 1.f, 0.f);
            g_B[i] = make_float4(1.f, 0.f, 0.f, 0.f);
            g_C[i] = make_float2(0.f, 0.f);
        }
    }
}

__global__ __launch_bounds__(128) void render_kernel(
    const int* __restrict__ wptr,
    float* __restrict__ out,
    int N, int pixels)
{
    __shared__ float4 sA[NMAX];
    __shared__ float4 sB[NMAX];
    __shared__ float2 sC[NMAX];

    for (int j = threadIdx.x; j < N; j += blockDim.x) {
        sA[j] = g_A[j];
        sB[j] = g_B[j];
        sC[j] = g_C[j];
    }
    __syncthreads();

    int p = blockIdx.x * blockDim.x + threadIdx.x;
    if (p >= pixels) return;
    int W = *wptr;
    float px = (float)(p % W) + 0.5f;
    float py = (float)(p / W) + 0.5f;

    float T = 1.0f;
    float r = 0.f, g = 0.f, b = 0.f, accW = 0.f, accD = 0.f;

    for (int j = 0; j < N; j++) {
        float4 A = sA[j];
        float dx = px - A.x;
        float dy = py - A.y;
        float4 B = sB[j];
        float sigma = 0.5f * (A.z * dx * dx + B.x * dy * dy) + A.w * dx * dy;
        // sigma>5.55 => alpha < exp(-5.55) < 1/255 for any op<=1 -> ref masks to 0 too
        if (sigma < 0.f || sigma > 5.55f) continue;
        float alpha = fminf(B.y * __expf(-sigma), 0.999f);
        if (alpha < (1.0f / 255.0f)) continue;
        float w = alpha * T;
        r += w * B.z;
        g += w * B.w;
        float2 C = sC[j];
        b += w * C.x;
        accD += w * C.y;
        accW += w;
        T *= (1.0f - alpha);
        if (T < 1e-5f) break;
    }

    float ed = accD / fmaxf(accW, 1e-10f);
    out[p * 4 + 0] = r;
    out[p * 4 + 1] = g;
    out[p * 4 + 2] = b;
    out[p * 4 + 3] = ed;
    out[pixels * 4 + p] = accW;
}

extern "C" void kernel_launch(void* const* d_in, const int* in_sizes, int n_in,
                              void* d_out, int out_size) {
    const float* means3d = (const float*)d_in[0];
    const float* quats   = (const float*)d_in[1];
    const float* scales  = (const float*)d_in[2];
    const float* opac    = (const float*)d_in[3];
    const float* sh      = (const float*)d_in[4];
    const float* c2w     = (const float*)d_in[5];
    const float* Ks      = (const float*)d_in[6];
    const int*   wptr    = (const int*)d_in[7];
    float* out = (float*)d_out;

    int N = in_sizes[0] / 3;
    if (N > NMAX) N = NMAX;
    int pixels = out_size / 5;

    preprocess_sort_kernel<<<1, NMAX>>>(means3d, quats, scales, opac, sh, c2w, Ks, N);

    int threads = 128;
    int blocks = (pixels + threads - 1) / threads;
    render_kernel<<<blocks, threads>>>(wptr, out, N, pixels);
}

// round 6
// speedup vs baseline: 3.1164x; 3.1164x over previous
#include <cuda_runtime.h>
#include <math.h>

#define NMAX 1024
#define TW 16
#define TH 8
#define BT 128   // threads per render block = TW*TH

static __device__ __forceinline__ float finf() { return __int_as_float(0x7f800000); }

// Sorted (render-ready) SoA scratch
__device__ float4 g_A[NMAX]; // mx, my, conA, conB
__device__ float4 g_B[NMAX]; // conC, op, colR, colG
__device__ float2 g_C[NMAX]; // colB, depth
__device__ float2 g_D[NMAX]; // rx, ry  (rx < 0 => culled)
// Unsorted scratch
__device__ float4 u_A[NMAX];
__device__ float4 u_B[NMAX];
__device__ float2 u_C[NMAX];
__device__ float2 u_D[NMAX];

__global__ __launch_bounds__(NMAX) void preprocess_sort_kernel(
    const float* __restrict__ means3d,   // [N,3]
    const float* __restrict__ quats,     // [N,4]
    const float* __restrict__ scales,    // [N,3]
    const float* __restrict__ opac,      // [N]
    const float* __restrict__ sh,        // [N,4,3]
    const float* __restrict__ c2w,       // [4,4]
    const float* __restrict__ Ks,        // [3,3]
    int N)
{
    const float SH_C0 = 0.28209479177387814f;
    const float SH_C1 = 0.4886025119029199f;
    const float NEARP = 0.01f;
    const float FARP  = 1e10f;
    const float LOWPASS = 0.3f;

    __shared__ float skey[NMAX];
    __shared__ int   sidx[NMAX];

    int i = threadIdx.x;
    float key = finf();

    if (i < N) {
        // viewmat = inv(camtoworld) (rigid): Rw = camR^T, tw = -Rw * camt
        float Rw[3][3];
        #pragma unroll
        for (int r = 0; r < 3; r++)
            #pragma unroll
            for (int c = 0; c < 3; c++)
                Rw[r][c] = c2w[c * 4 + r];
        float ct0 = c2w[3], ct1 = c2w[7], ct2 = c2w[11];
        float tw[3];
        #pragma unroll
        for (int r = 0; r < 3; r++)
            tw[r] = -(Rw[r][0] * ct0 + Rw[r][1] * ct1 + Rw[r][2] * ct2);

        float fx = Ks[0], cx = Ks[2], fy = Ks[4], cy = Ks[5];

        float m0 = means3d[i * 3 + 0], m1 = means3d[i * 3 + 1], m2 = means3d[i * 3 + 2];
        float x = Rw[0][0] * m0 + Rw[0][1] * m1 + Rw[0][2] * m2 + tw[0];
        float y = Rw[1][0] * m0 + Rw[1][1] * m1 + Rw[1][2] * m2 + tw[1];
        float z = Rw[2][0] * m0 + Rw[2][1] * m1 + Rw[2][2] * m2 + tw[2];

        bool valid = (z > NEARP) && (z < FARP);
        float zs = valid ? z : 1.0f;
        float m2x = fx * x / zs + cx;
        float m2y = fy * y / zs + cy;

        // quat -> rotmat
        float qw = quats[i * 4 + 0], qx = quats[i * 4 + 1], qy = quats[i * 4 + 2], qz = quats[i * 4 + 3];
        float qn = rsqrtf(qw * qw + qx * qx + qy * qy + qz * qz);
        qw *= qn; qx *= qn; qy *= qn; qz *= qn;
        float Rg[3][3];
        Rg[0][0] = 1.f - 2.f * (qy * qy + qz * qz);
        Rg[0][1] = 2.f * (qx * qy - qw * qz);
        Rg[0][2] = 2.f * (qx * qz + qw * qy);
        Rg[1][0] = 2.f * (qx * qy + qw * qz);
        Rg[1][1] = 1.f - 2.f * (qx * qx + qz * qz);
        Rg[1][2] = 2.f * (qy * qz - qw * qx);
        Rg[2][0] = 2.f * (qx * qz - qw * qy);
        Rg[2][1] = 2.f * (qy * qz + qw * qx);
        Rg[2][2] = 1.f - 2.f * (qx * qx + qy * qy);

        float s0 = scales[i * 3 + 0], s1 = scales[i * 3 + 1], s2v = scales[i * 3 + 2];
        float sq[3] = { s0 * s0, s1 * s1, s2v * s2v };

        // cov3d = (Rg * diag(s)) (Rg * diag(s))^T
        float cov3[3][3];
        #pragma unroll
        for (int r = 0; r < 3; r++)
            #pragma unroll
            for (int c = 0; c < 3; c++)
                cov3[r][c] = Rg[r][0] * Rg[c][0] * sq[0]
                           + Rg[r][1] * Rg[c][1] * sq[1]
                           + Rg[r][2] * Rg[c][2] * sq[2];

        // cov_cam = Rw cov3 Rw^T
        float Vc[3][3];
        #pragma unroll
        for (int r = 0; r < 3; r++)
            #pragma unroll
            for (int c = 0; c < 3; c++)
                Vc[r][c] = Rw[r][0] * cov3[0][c] + Rw[r][1] * cov3[1][c] + Rw[r][2] * cov3[2][c];
        float cc[3][3];
        #pragma unroll
        for (int r = 0; r < 3; r++)
            #pragma unroll
            for (int c = 0; c < 3; c++)
                cc[r][c] = Vc[r][0] * Rw[c][0] + Vc[r][1] * Rw[c][1] + Vc[r][2] * Rw[c][2];

        // J (2x3), cov2d = J cov_cam J^T
        float j00 = fx / zs, j02 = -fx * x / (zs * zs);
        float j11 = fy / zs, j12 = -fy * y / (zs * zs);
        float a = j00 * (cc[0][0] * j00 + cc[0][2] * j02)
                + j02 * (cc[2][0] * j00 + cc[2][2] * j02);
        float b = j00 * (cc[0][1] * j11 + cc[0][2] * j12)
                + j02 * (cc[2][1] * j11 + cc[2][2] * j12);
        float c = j11 * (cc[1][1] * j11 + cc[1][2] * j12)
                + j12 * (cc[2][1] * j11 + cc[2][2] * j12);
        a += LOWPASS;
        c += LOWPASS;
        float det = a * c - b * b;
        valid = valid && (det > 0.f);
        float dets = (det > 0.f) ? det : 1.0f;
        float conA = c / dets, conB = -b / dets, conC = a / dets;

        // SH degree-1 color
        float dx3 = m0 - ct0, dy3 = m1 - ct1, dz3 = m2 - ct2;
        float dn = sqrtf(dx3 * dx3 + dy3 * dy3 + dz3 * dz3);
        dn = fmaxf(dn, 1e-8f);
        float dxn = dx3 / dn, dyn = dy3 / dn, dzn = dz3 / dn;
        float col[3];
        #pragma unroll
        for (int ch = 0; ch < 3; ch++) {
            float v = SH_C0 * sh[i * 12 + ch]
                    - SH_C1 * dyn * sh[i * 12 + 3 + ch]
                    + SH_C1 * dzn * sh[i * 12 + 6 + ch]
                    - SH_C1 * dxn * sh[i * 12 + 9 + ch];
            col[ch] = fmaxf(v + 0.5f, 0.0f);
        }

        float op = 1.0f / (1.0f + __expf(-opac[i]));
        op = valid ? op : 0.0f;

        // Opacity-aware ellipse AABB half-extents.
        // alpha = op*exp(-sigma) >= 1/255  <=>  sigma <= ln(255*op).
        // Ellipse sigma <= s has AABB half-extents sqrt(2 s a), sqrt(2 s c)
        // (a, c are cov2d diagonal entries incl. lowpass; conC/detCon = a etc.)
        float rx = -1.f, ry = -1.f;
        if (valid && op * 255.f > 1.0f) {
            float sg = fminf(5.55f, logf(255.f * op));
            rx = sqrtf(2.f * sg * a);
            ry = sqrtf(2.f * sg * c);
        } else {
            op = 0.f;
        }

        u_A[i] = make_float4(m2x, m2y, conA, conB);
        u_B[i] = make_float4(conC, op, col[0], col[1]);
        u_C[i] = make_float2(col[2], z);
        u_D[i] = make_float2(rx, ry);

        key = (valid && op > 0.f) ? z : finf();
    }

    skey[i] = key;
    sidx[i] = i;
    __syncthreads();

    // Bitonic sort, ascending by key
    for (int k = 2; k <= NMAX; k <<= 1) {
        for (int j = k >> 1; j > 0; j >>= 1) {
            int p = i ^ j;
            if (p > i) {
                bool up = ((i & k) == 0);
                float ka = skey[i], kb = skey[p];
                bool swap = up ? (ka > kb) : (ka < kb);
                if (swap) {
                    int ia = sidx[i];
                    skey[i] = kb; skey[p] = ka;
                    sidx[i] = sidx[p]; sidx[p] = ia;
                }
            }
            __syncthreads();
        }
    }

    // Gather sorted SoA
    if (i < N) {
        int s = sidx[i];
        if (s < N) {
            g_A[i] = u_A[s];
            g_B[i] = u_B[s];
            g_C[i] = u_C[s];
            g_D[i] = u_D[s];
        } else {
            g_A[i] = make_float4(0.f, 0.f, 1.f, 0.f);
            g_B[i] = make_float4(1.f, 0.f, 0.f, 0.f);
            g_C[i] = make_float2(0.f, 0.f);
            g_D[i] = make_float2(-1.f, -1.f);
        }
    }
}

__global__ __launch_bounds__(BT) void render_kernel(
    const int* __restrict__ wptr,
    float* __restrict__ out,
    int N, int pixels)
{
    __shared__ float4 cA[BT];
    __shared__ float4 cB[BT];
    __shared__ float2 cC[BT];
    __shared__ int    warpCnt[BT / 32];

    const int tid  = threadIdx.x;
    const int warp = tid >> 5;
    const int lane = tid & 31;

    const int W = *wptr;
    const int H = pixels / W;
    const int tilesX = (W + TW - 1) / TW;
    const int tilesY = (H + TH - 1) / TH;
    const int tileCount = tilesX * tilesY;

    for (int t = blockIdx.x; t < tileCount; t += gridDim.x) {
        int tx = t % tilesX;
        int ty = t / tilesX;
        int x0 = tx * TW;
        int y0 = ty * TH;

        int pxI = x0 + (tid & (TW - 1));
        int pyI = y0 + (tid / TW);
        bool inb = (pxI < W) && (pyI < H);
        float px = (float)pxI + 0.5f;
        float py = (float)pyI + 0.5f;

        // tile rect (pixel centers live in [x0+0.5, x0+TW-0.5]; use outer rect, conservative)
        float xlo = (float)x0,        xhi = (float)(x0 + TW);
        float ylo = (float)y0,        yhi = (float)(y0 + TH);

        float T = 1.0f;
        float r = 0.f, g = 0.f, b = 0.f, accW = 0.f, accD = 0.f;

        for (int chunk = 0; chunk < N; chunk += BT) {
            int gi = chunk + tid;
            bool pred = false;
            float4 A;
            if (gi < N) {
                float2 R = g_D[gi];
                if (R.x >= 0.f) {
                    A = g_A[gi];
                    pred = (A.x + R.x >= xlo) && (A.x - R.x <= xhi) &&
                           (A.y + R.y >= ylo) && (A.y - R.y <= yhi);
                }
            }
            unsigned m = __ballot_sync(0xffffffffu, pred);
            if (lane == 0) warpCnt[warp] = __popc(m);
            __syncthreads();

            int base = 0;
            #pragma unroll
            for (int wI = 0; wI < BT / 32; wI++)
                if (wI < warp) base += warpCnt[wI];
            int total = 0;
            #pragma unroll
            for (int wI = 0; wI < BT / 32; wI++) total += warpCnt[wI];

            if (pred) {
                int off = base + __popc(m & ((1u << lane) - 1u));
                cA[off] = A;
                cB[off] = g_B[gi];
                cC[off] = g_C[gi];
            }
            __syncthreads();

            if (inb && T >= 1e-5f) {
                for (int j = 0; j < total; j++) {
                    float4 Aa = cA[j];
                    float dx = px - Aa.x;
                    float dy = py - Aa.y;
                    float4 Bb = cB[j];
                    float sigma = 0.5f * (Aa.z * dx * dx + Bb.x * dy * dy) + Aa.w * dx * dy;
                    if (sigma < 0.f || sigma > 5.55f) continue;
                    float alpha = fminf(Bb.y * __expf(-sigma), 0.999f);
                    if (alpha < (1.0f / 255.0f)) continue;
                    float w = alpha * T;
                    r += w * Bb.z;
                    g += w * Bb.w;
                    float2 Cc = cC[j];
                    b += w * Cc.x;
                    accD += w * Cc.y;
                    accW += w;
                    T *= (1.0f - alpha);
                    if (T < 1e-5f) break;
                }
            }

            int alive = __syncthreads_count(inb && T >= 1e-5f);
            if (alive == 0) break;
        }

        if (inb) {
            int p = pyI * W + pxI;
            float ed = accD / fmaxf(accW, 1e-10f);
            out[p * 4 + 0] = r;
            out[p * 4 + 1] = g;
            out[p * 4 + 2] = b;
            out[p * 4 + 3] = ed;
            out[pixels * 4 + p] = accW;
        }
    }
}

extern "C" void kernel_launch(void* const* d_in, const int* in_sizes, int n_in,
                              void* d_out, int out_size) {
    const float* means3d = (const float*)d_in[0];
    const float* quats   = (const float*)d_in[1];
    const float* scales  = (const float*)d_in[2];
    const float* opac    = (const float*)d_in[3];
    const float* sh      = (const float*)d_in[4];
    const float* c2w     = (const float*)d_in[5];
    const float* Ks      = (const float*)d_in[6];
    const int*   wptr    = (const int*)d_in[7];
    float* out = (float*)d_out;

    int N = in_sizes[0] / 3;
    if (N > NMAX) N = NMAX;
    int pixels = out_size / 5;

    preprocess_sort_kernel<<<1, NMAX>>>(means3d, quats, scales, opac, sh, c2w, Ks, N);

    // one block per (typical) tile; grid-stride in-kernel covers any W,H split
    int blocks = (pixels + BT - 1) / BT;
    if (blocks < 1) blocks = 1;
    render_kernel<<<blocks, BT>>>(wptr, out, N, pixels);
}

// round 9
// speedup vs baseline: 3.3205x; 1.0655x over previous
#include <cuda_runtime.h>
#include <math.h>

#define NMAX  1024
#define TW    16
#define TH    8
#define BT    128   // threads per render block = TW*TH
#define CHUNK 256   // gaussians tested per render chunk (2 per thread)

static __device__ __forceinline__ float finf() { return __int_as_float(0x7f800000); }

// Sorted (render-ready) SoA
__device__ float4 g_A[NMAX]; // mx, my, conA, conB
__device__ float4 g_B[NMAX]; // conC, op, colR, colG
__device__ float2 g_C[NMAX]; // colB, depth
__device__ float4 g_D[NMAX]; // xmin, xmax, ymin, ymax  (screen AABB; culled => empty box)
// Unsorted scratch
__device__ float4 u_A[NMAX];
__device__ float4 u_B[NMAX];
__device__ float2 u_C[NMAX];
__device__ float4 u_D[NMAX];
__device__ float  u_key[NMAX];

// ---------------------------------------------------------------------------
// Per-gaussian preprocess, parallel across the grid.
// ---------------------------------------------------------------------------
__global__ __launch_bounds__(128) void preprocess_kernel(
    const float* __restrict__ means3d,   // [N,3]
    const float* __restrict__ quats,     // [N,4]
    const float* __restrict__ scales,    // [N,3]
    const float* __restrict__ opac,      // [N]
    const float* __restrict__ sh,        // [N,4,3]
    const float* __restrict__ c2w,       // [4,4]
    const float* __restrict__ Ks,        // [3,3]
    int N)
{
    const float SH_C0 = 0.28209479177387814f;
    const float SH_C1 = 0.4886025119029199f;
    const float NEARP = 0.01f;
    const float FARP  = 1e10f;
    const float LOWPASS = 0.3f;

    int i = blockIdx.x * blockDim.x + threadIdx.x;
    if (i >= N) return;

    // viewmat = inv(camtoworld) (rigid): Rw = camR^T, tw = -Rw * camt
    float Rw[3][3];
    #pragma unroll
    for (int r = 0; r < 3; r++)
        #pragma unroll
        for (int c = 0; c < 3; c++)
            Rw[r][c] = c2w[c * 4 + r];
    float ct0 = c2w[3], ct1 = c2w[7], ct2 = c2w[11];
    float tw[3];
    #pragma unroll
    for (int r = 0; r < 3; r++)
        tw[r] = -(Rw[r][0] * ct0 + Rw[r][1] * ct1 + Rw[r][2] * ct2);

    float fx = Ks[0], cx = Ks[2], fy = Ks[4], cy = Ks[5];

    float m0 = means3d[i * 3 + 0], m1 = means3d[i * 3 + 1], m2 = means3d[i * 3 + 2];
    float x = Rw[0][0] * m0 + Rw[0][1] * m1 + Rw[0][2] * m2 + tw[0];
    float y = Rw[1][0] * m0 + Rw[1][1] * m1 + Rw[1][2] * m2 + tw[1];
    float z = Rw[2][0] * m0 + Rw[2][1] * m1 + Rw[2][2] * m2 + tw[2];

    bool valid = (z > NEARP) && (z < FARP);
    float zs = valid ? z : 1.0f;
    float m2x = fx * x / zs + cx;
    float m2y = fy * y / zs + cy;

    // quat -> rotmat
    float qw = quats[i * 4 + 0], qx = quats[i * 4 + 1], qy = quats[i * 4 + 2], qz = quats[i * 4 + 3];
    float qn = rsqrtf(qw * qw + qx * qx + qy * qy + qz * qz);
    qw *= qn; qx *= qn; qy *= qn; qz *= qn;
    float Rg[3][3];
    Rg[0][0] = 1.f - 2.f * (qy * qy + qz * qz);
    Rg[0][1] = 2.f * (qx * qy - qw * qz);
    Rg[0][2] = 2.f * (qx * qz + qw * qy);
    Rg[1][0] = 2.f * (qx * qy + qw * qz);
    Rg[1][1] = 1.f - 2.f * (qx * qx + qz * qz);
    Rg[1][2] = 2.f * (qy * qz - qw * qx);
    Rg[2][0] = 2.f * (qx * qz - qw * qy);
    Rg[2][1] = 2.f * (qy * qz + qw * qx);
    Rg[2][2] = 1.f - 2.f * (qx * qx + qy * qy);

    float s0 = scales[i * 3 + 0], s1 = scales[i * 3 + 1], s2v = scales[i * 3 + 2];
    float sq[3] = { s0 * s0, s1 * s1, s2v * s2v };

    // cov3d = (Rg * diag(s)) (Rg * diag(s))^T
    float cov3[3][3];
    #pragma unroll
    for (int r = 0; r < 3; r++)
        #pragma unroll
        for (int c = 0; c < 3; c++)
            cov3[r][c] = Rg[r][0] * Rg[c][0] * sq[0]
                       + Rg[r][1] * Rg[c][1] * sq[1]
                       + Rg[r][2] * Rg[c][2] * sq[2];

    // cov_cam = Rw cov3 Rw^T
    float Vc[3][3];
    #pragma unroll
    for (int r = 0; r < 3; r++)
        #pragma unroll
        for (int c = 0; c < 3; c++)
            Vc[r][c] = Rw[r][0] * cov3[0][c] + Rw[r][1] * cov3[1][c] + Rw[r][2] * cov3[2][c];
    float cc[3][3];
    #pragma unroll
    for (int r = 0; r < 3; r++)
        #pragma unroll
        for (int c = 0; c < 3; c++)
            cc[r][c] = Vc[r][0] * Rw[c][0] + Vc[r][1] * Rw[c][1] + Vc[r][2] * Rw[c][2];

    // J (2x3), cov2d = J cov_cam J^T
    float j00 = fx / zs, j02 = -fx * x / (zs * zs);
    float j11 = fy / zs, j12 = -fy * y / (zs * zs);
    float a = j00 * (cc[0][0] * j00 + cc[0][2] * j02)
            + j02 * (cc[2][0] * j00 + cc[2][2] * j02);
    float b = j00 * (cc[0][1] * j11 + cc[0][2] * j12)
            + j02 * (cc[2][1] * j11 + cc[2][2] * j12);
    float c = j11 * (cc[1][1] * j11 + cc[1][2] * j12)
            + j12 * (cc[2][1] * j11 + cc[2][2] * j12);
    a += LOWPASS;
    c += LOWPASS;
    float det = a * c - b * b;
    valid = valid && (det > 0.f);
    float dets = (det > 0.f) ? det : 1.0f;
    float conA = c / dets, conB = -b / dets, conC = a / dets;

    // SH degree-1 color
    float dx3 = m0 - ct0, dy3 = m1 - ct1, dz3 = m2 - ct2;
    float dn = sqrtf(dx3 * dx3 + dy3 * dy3 + dz3 * dz3);
    dn = fmaxf(dn, 1e-8f);
    float dxn = dx3 / dn, dyn = dy3 / dn, dzn = dz3 / dn;
    float col[3];
    #pragma unroll
    for (int ch = 0; ch < 3; ch++) {
        float v = SH_C0 * sh[i * 12 + ch]
                - SH_C1 * dyn * sh[i * 12 + 3 + ch]
                + SH_C1 * dzn * sh[i * 12 + 6 + ch]
                - SH_C1 * dxn * sh[i * 12 + 9 + ch];
        col[ch] = fmaxf(v + 0.5f, 0.0f);
    }

    float op = 1.0f / (1.0f + __expf(-opac[i]));
    op = valid ? op : 0.0f;

    // Opacity-aware screen AABB: alpha >= 1/255 <=> sigma <= ln(255*op).
    // Ellipse sigma<=s AABB half-extents: sqrt(2 s a), sqrt(2 s c).
    float xmin = 1e30f, xmax = -1e30f, ymin = 1e30f, ymax = -1e30f;
    if (valid && op * 255.f > 1.0f) {
        float sg = fminf(5.55f, logf(255.f * op));
        float rx = sqrtf(2.f * sg * a);
        float ry = sqrtf(2.f * sg * c);
        xmin = m2x - rx; xmax = m2x + rx;
        ymin = m2y - ry; ymax = m2y + ry;
    } else {
        op = 0.f;
    }

    u_A[i] = make_float4(m2x, m2y, conA, conB);
    u_B[i] = make_float4(conC, op, col[0], col[1]);
    u_C[i] = make_float2(col[2], z);
    u_D[i] = make_float4(xmin, xmax, ymin, ymax);
    u_key[i] = (valid && op > 0.f) ? z : finf();
}

// ---------------------------------------------------------------------------
// Stable rank-sort (O(N^2) comparisons, grid-parallel) + scatter into sorted SoA.
// rank_i = #{j : key_j < key_i} + #{j < i : key_j == key_i}  == stable argsort pos.
// ---------------------------------------------------------------------------
__global__ __launch_bounds__(128) void rank_scatter_kernel(int N)
{
    __shared__ float sk[NMAX];
    for (int j = threadIdx.x; j < N; j += blockDim.x) sk[j] = u_key[j];
    __syncthreads();

    int i = blockIdx.x * blockDim.x + threadIdx.x;
    if (i >= N) return;
    float ki = sk[i];
    int rank = 0;
    #pragma unroll 8
    for (int j = 0; j < N; j++) {
        float kj = sk[j];
        rank += (kj < ki) || ((kj == ki) && (j < i));
    }
    g_A[rank] = u_A[i];
    g_B[rank] = u_B[i];
    g_C[rank] = u_C[i];
    g_D[rank] = u_D[i];
}

// ---------------------------------------------------------------------------
// Tile-based render: ordered-compact survivors per 256-gaussian chunk, composite.
// ---------------------------------------------------------------------------
__global__ __launch_bounds__(BT) void render_kernel(
    const int* __restrict__ wptr,
    float* __restrict__ out,
    int N, int pixels)
{
    __shared__ float4 cA[CHUNK];
    __shared__ float4 cB[CHUNK];
    __shared__ float2 cC[CHUNK];
    __shared__ int    warpCnt[8];   // [0..3]: first half per warp, [4..7]: second half

    const int tid  = threadIdx.x;
    const int warp = tid >> 5;
    const int lane = tid & 31;

    const int W = *wptr;
    const int H = pixels / W;
    const int tilesX = (W + TW - 1) / TW;
    const int tilesY = (H + TH - 1) / TH;
    const int tileCount = tilesX * tilesY;

    for (int t = blockIdx.x; t < tileCount; t += gridDim.x) {
        int tx = t % tilesX;
        int ty = t / tilesX;
        int x0 = tx * TW;
        int y0 = ty * TH;

        int pxI = x0 + (tid & (TW - 1));
        int pyI = y0 + (tid / TW);
        bool inb = (pxI < W) && (pyI < H);
        float px = (float)pxI + 0.5f;
        float py = (float)pyI + 0.5f;

        float xlo = (float)x0, xhi = (float)(x0 + TW);
        float ylo = (float)y0, yhi = (float)(y0 + TH);

        float T = 1.0f;
        float r = 0.f, g = 0.f, b = 0.f, accW = 0.f, accD = 0.f;

        for (int chunk = 0; chunk < N; chunk += CHUNK) {
            int gi0 = chunk + tid;
            int gi1 = chunk + BT + tid;
            bool p0 = false, p1 = false;
            if (gi0 < N) {
                float4 D = g_D[gi0];
                p0 = (D.y >= xlo) && (D.x <= xhi) && (D.w >= ylo) && (D.z <= yhi);
            }
            if (gi1 < N) {
                float4 D = g_D[gi1];
                p1 = (D.y >= xlo) && (D.x <= xhi) && (D.w >= ylo) && (D.z <= yhi);
            }
            unsigned m0 = __ballot_sync(0xffffffffu, p0);
            unsigned m1 = __ballot_sync(0xffffffffu, p1);
            if (lane == 0) {
                warpCnt[warp]     = __popc(m0);
                warpCnt[4 + warp] = __popc(m1);
            }
            __syncthreads();

            int c0 = warpCnt[0], c1 = warpCnt[1], c2 = warpCnt[2], c3 = warpCnt[3];
            int c4 = warpCnt[4], c5 = warpCnt[5], c6 = warpCnt[6], c7 = warpCnt[7];
            int half0 = c0 + c1 + c2 + c3;
            int total = half0 + c4 + c5 + c6 + c7;
            int base0 = 0, base1 = half0;
            if (warp > 0) { base0 += c0; base1 += c4; }
            if (warp > 1) { base0 += c1; base1 += c5; }
            if (warp > 2) { base0 += c2; base1 += c6; }

            if (p0) {
                int off = base0 + __popc(m0 & ((1u << lane) - 1u));
                cA[off] = g_A[gi0];
                cB[off] = g_B[gi0];
                cC[off] = g_C[gi0];
            }
            if (p1) {
                int off = base1 + __popc(m1 & ((1u << lane) - 1u));
                cA[off] = g_A[gi1];
                cB[off] = g_B[gi1];
                cC[off] = g_C[gi1];
            }
            __syncthreads();

            if (inb && T >= 1e-5f) {
                for (int j = 0; j < total; j++) {
                    float4 Aa = cA[j];
                    float dx = px - Aa.x;
                    float dy = py - Aa.y;
                    float4 Bb = cB[j];
                    float sigma = 0.5f * (Aa.z * dx * dx + Bb.x * dy * dy) + Aa.w * dx * dy;
                    if (sigma < 0.f || sigma > 5.55f) continue;
                    float alpha = fminf(Bb.y * __expf(-sigma), 0.999f);
                    if (alpha < (1.0f / 255.0f)) continue;
                    float w = alpha * T;
                    r += w * Bb.z;
                    g += w * Bb.w;
                    float2 Cc = cC[j];
                    b += w * Cc.x;
                    accD += w * Cc.y;
                    accW += w;
                    T *= (1.0f - alpha);
                    if (T < 1e-5f) break;
                }
            }

            int alive = __syncthreads_count(inb && T >= 1e-5f);
            if (alive == 0) break;
        }

        if (inb) {
            int p = pyI * W + pxI;
            float ed = accD / fmaxf(accW, 1e-10f);
            out[p * 4 + 0] = r;
            out[p * 4 + 1] = g;
            out[p * 4 + 2] = b;
            out[p * 4 + 3] = ed;
            out[pixels * 4 + p] = accW;
        }
    }
}

extern "C" void kernel_launch(void* const* d_in, const int* in_sizes, int n_in,
                              void* d_out, int out_size) {
    const float* means3d = (const float*)d_in[0];
    const float* quats   = (const float*)d_in[1];
    const float* scales  = (const float*)d_in[2];
    const float* opac    = (const float*)d_in[3];
    const float* sh      = (const float*)d_in[4];
    const float* c2w     = (const float*)d_in[5];
    const float* Ks      = (const float*)d_in[6];
    const int*   wptr    = (const int*)d_in[7];
    float* out = (float*)d_out;

    int N = in_sizes[0] / 3;
    if (N > NMAX) N = NMAX;
    int pixels = out_size / 5;

    int pblocks = (N + 127) / 128;
    preprocess_kernel<<<pblocks, 128>>>(means3d, quats, scales, opac, sh, c2w, Ks, N);
    rank_scatter_kernel<<<pblocks, 128>>>(N);

    int blocks = (pixels + BT - 1) / BT;
    if (blocks < 1) blocks = 1;
    render_kernel<<<blocks, BT>>>(wptr, out, N, pixels);
}

// round 10
// speedup vs baseline: 3.5891x; 1.0809x over previous
#include <cuda_runtime.h>
#include <math.h>

#define NMAX  1024
#define TW    16
#define TH    8
#define BT    128            // render block threads = TW*TH
#define ROUNDS (NMAX / BT)   // 8 cull rounds

static __device__ __forceinline__ float finf() { return __int_as_float(0x7f800000); }

// Sorted (render-ready) SoA
__device__ float4 g_A[NMAX]; // mx, my, conA, conB
__device__ float4 g_B[NMAX]; // conC, op, colR, colG
__device__ float2 g_C[NMAX]; // colB, depth
__device__ float4 g_D[NMAX]; // xmin, xmax, ymin, ymax (screen AABB; culled => empty box)
// Key exchange buffer (only 4B/gaussian crosses CTAs)
__device__ float  k_buf[NMAX];

// ---------------------------------------------------------------------------
// Fused preprocess + stable rank-sort + scatter. One 8-CTA cluster, payload
// stays in registers; only keys round-trip through global.
// ---------------------------------------------------------------------------
__global__ __launch_bounds__(128) __cluster_dims__(8, 1, 1)
void preprocess_rank_kernel(
    const float* __restrict__ means3d,   // [N,3]
    const float* __restrict__ quats,     // [N,4]
    const float* __restrict__ scales,    // [N,3]
    const float* __restrict__ opac,      // [N]
    const float* __restrict__ sh,        // [N,4,3]
    const float* __restrict__ c2w,       // [4,4]
    const float* __restrict__ Ks,        // [3,3]
    int N)
{
    const float SH_C0 = 0.28209479177387814f;
    const float SH_C1 = 0.4886025119029199f;
    const float NEARP = 0.01f;
    const float FARP  = 1e10f;
    const float LOWPASS = 0.3f;

    __shared__ float skey[NMAX];

    int i = blockIdx.x * blockDim.x + threadIdx.x;   // 0..1023

    float4 oA, oB, oD;
    float2 oC;
    float  key = finf();

    if (i < N) {
        // Fire the per-gaussian loads early (vectorized where layout allows)
        const float4 q4  = *(const float4*)(quats + i * 4);
        const float4 sh0 = *(const float4*)(sh + i * 12);
        const float4 sh1 = *(const float4*)(sh + i * 12 + 4);
        const float4 sh2 = *(const float4*)(sh + i * 12 + 8);
        float m0 = means3d[i * 3 + 0], m1 = means3d[i * 3 + 1], m2 = means3d[i * 3 + 2];
        float s0 = scales[i * 3 + 0], s1 = scales[i * 3 + 1], s2v = scales[i * 3 + 2];
        float opraw = opac[i];

        // viewmat = inv(camtoworld) (rigid): Rw = camR^T, tw = -Rw * camt
        float Rw[3][3];
        #pragma unroll
        for (int r = 0; r < 3; r++)
            #pragma unroll
            for (int c = 0; c < 3; c++)
                Rw[r][c] = c2w[c * 4 + r];
        float ct0 = c2w[3], ct1 = c2w[7], ct2 = c2w[11];
        float tw[3];
        #pragma unroll
        for (int r = 0; r < 3; r++)
            tw[r] = -(Rw[r][0] * ct0 + Rw[r][1] * ct1 + Rw[r][2] * ct2);

        float fx = Ks[0], cx = Ks[2], fy = Ks[4], cy = Ks[5];

        float x = Rw[0][0] * m0 + Rw[0][1] * m1 + Rw[0][2] * m2 + tw[0];
        float y = Rw[1][0] * m0 + Rw[1][1] * m1 + Rw[1][2] * m2 + tw[1];
        float z = Rw[2][0] * m0 + Rw[2][1] * m1 + Rw[2][2] * m2 + tw[2];

        bool valid = (z > NEARP) && (z < FARP);
        float zs = valid ? z : 1.0f;
        float m2x = fx * x / zs + cx;
        float m2y = fy * y / zs + cy;

        // quat -> rotmat
        float qw = q4.x, qx = q4.y, qy = q4.z, qz = q4.w;
        float qn = rsqrtf(qw * qw + qx * qx + qy * qy + qz * qz);
        qw *= qn; qx *= qn; qy *= qn; qz *= qn;
        float Rg[3][3];
        Rg[0][0] = 1.f - 2.f * (qy * qy + qz * qz);
        Rg[0][1] = 2.f * (qx * qy - qw * qz);
        Rg[0][2] = 2.f * (qx * qz + qw * qy);
        Rg[1][0] = 2.f * (qx * qy + qw * qz);
        Rg[1][1] = 1.f - 2.f * (qx * qx + qz * qz);
        Rg[1][2] = 2.f * (qy * qz - qw * qx);
        Rg[2][0] = 2.f * (qx * qz - qw * qy);
        Rg[2][1] = 2.f * (qy * qz + qw * qx);
        Rg[2][2] = 1.f - 2.f * (qx * qx + qy * qy);

        float sq[3] = { s0 * s0, s1 * s1, s2v * s2v };

        // cov3d = (Rg * diag(s)) (Rg * diag(s))^T
        float cov3[3][3];
        #pragma unroll
        for (int r = 0; r < 3; r++)
            #pragma unroll
            for (int c = 0; c < 3; c++)
                cov3[r][c] = Rg[r][0] * Rg[c][0] * sq[0]
                           + Rg[r][1] * Rg[c][1] * sq[1]
                           + Rg[r][2] * Rg[c][2] * sq[2];

        // cov_cam = Rw cov3 Rw^T
        float Vc[3][3];
        #pragma unroll
        for (int r = 0; r < 3; r++)
            #pragma unroll
            for (int c = 0; c < 3; c++)
                Vc[r][c] = Rw[r][0] * cov3[0][c] + Rw[r][1] * cov3[1][c] + Rw[r][2] * cov3[2][c];
        float cc[3][3];
        #pragma unroll
        for (int r = 0; r < 3; r++)
            #pragma unroll
            for (int c = 0; c < 3; c++)
                cc[r][c] = Vc[r][0] * Rw[c][0] + Vc[r][1] * Rw[c][1] + Vc[r][2] * Rw[c][2];

        // J (2x3), cov2d = J cov_cam J^T
        float j00 = fx / zs, j02 = -fx * x / (zs * zs);
        float j11 = fy / zs, j12 = -fy * y / (zs * zs);
        float a = j00 * (cc[0][0] * j00 + cc[0][2] * j02)
                + j02 * (cc[2][0] * j00 + cc[2][2] * j02);
        float b = j00 * (cc[0][1] * j11 + cc[0][2] * j12)
                + j02 * (cc[2][1] * j11 + cc[2][2] * j12);
        float c = j11 * (cc[1][1] * j11 + cc[1][2] * j12)
                + j12 * (cc[2][1] * j11 + cc[2][2] * j12);
        a += LOWPASS;
        c += LOWPASS;
        float det = a * c - b * b;
        valid = valid && (det > 0.f);
        float dets = (det > 0.f) ? det : 1.0f;
        float conA = c / dets, conB = -b / dets, conC = a / dets;

        // SH degree-1 color
        float dx3 = m0 - ct0, dy3 = m1 - ct1, dz3 = m2 - ct2;
        float dn = sqrtf(dx3 * dx3 + dy3 * dy3 + dz3 * dz3);
        dn = fmaxf(dn, 1e-8f);
        float dxn = dx3 / dn, dyn = dy3 / dn, dzn = dz3 / dn;
        float shv[12] = { sh0.x, sh0.y, sh0.z, sh0.w, sh1.x, sh1.y, sh1.z, sh1.w,
                          sh2.x, sh2.y, sh2.z, sh2.w };
        float col[3];
        #pragma unroll
        for (int ch = 0; ch < 3; ch++) {
            float v = SH_C0 * shv[ch]
                    - SH_C1 * dyn * shv[3 + ch]
                    + SH_C1 * dzn * shv[6 + ch]
                    - SH_C1 * dxn * shv[9 + ch];
            col[ch] = fmaxf(v + 0.5f, 0.0f);
        }

        float op = 1.0f / (1.0f + __expf(-opraw));
        op = valid ? op : 0.0f;

        // Opacity-aware screen AABB: alpha >= 1/255 <=> sigma <= ln(255*op).
        float xmin = 1e30f, xmax = -1e30f, ymin = 1e30f, ymax = -1e30f;
        if (valid && op * 255.f > 1.0f) {
            float sg = fminf(5.55f, logf(255.f * op));
            float rx = sqrtf(2.f * sg * a);
            float ry = sqrtf(2.f * sg * c);
            xmin = m2x - rx; xmax = m2x + rx;
            ymin = m2y - ry; ymax = m2y + ry;
        } else {
            op = 0.f;
        }

        oA = make_float4(m2x, m2y, conA, conB);
        oB = make_float4(conC, op, col[0], col[1]);
        oC = make_float2(col[2], z);
        oD = make_float4(xmin, xmax, ymin, ymax);
        key = (valid && op > 0.f) ? z : finf();
    } else {
        oA = make_float4(0.f, 0.f, 1.f, 0.f);
        oB = make_float4(1.f, 0.f, 0.f, 0.f);
        oC = make_float2(0.f, 0.f);
        oD = make_float4(1e30f, -1e30f, 1e30f, -1e30f);
    }

    // Publish key, make visible cluster-wide, sync the 8 CTAs.
    k_buf[i] = key;
    __threadfence();
    asm volatile("barrier.cluster.arrive.aligned;" ::: "memory");
    asm volatile("barrier.cluster.wait.aligned;" ::: "memory");

    // Load all keys into local smem (each thread: 2 float4 loads)
    {
        float4* sk4 = (float4*)skey;
        const float4* kb4 = (const float4*)k_buf;
        int t = threadIdx.x;
        sk4[t]       = kb4[t];
        sk4[t + 128] = kb4[t + 128];
    }
    __syncthreads();

    // Stable rank: rank = #{j: kj<ki} + #{j<i: kj==ki}
    int rank = 0;
    {
        const float4* sk4 = (const float4*)skey;
        #pragma unroll 4
        for (int j4 = 0; j4 < NMAX / 4; j4++) {
            float4 k = sk4[j4];
            int j = j4 * 4;
            rank += (k.x < key) || ((k.x == key) && (j + 0 < i));
            rank += (k.y < key) || ((k.y == key) && (j + 1 < i));
            rank += (k.z < key) || ((k.z == key) && (j + 2 < i));
            rank += (k.w < key) || ((k.w == key) && (j + 3 < i));
        }
    }

    g_A[rank] = oA;
    g_B[rank] = oB;
    g_C[rank] = oC;
    g_D[rank] = oD;
}

// ---------------------------------------------------------------------------
// Tile render: all cull rounds up front (2 barriers total), then a
// barrier-free front-to-back composite with warp-uniform early exit.
// ---------------------------------------------------------------------------
__global__ __launch_bounds__(BT) void render_kernel(
    const int* __restrict__ wptr,
    float* __restrict__ out,
    int N, int pixels)
{
    __shared__ float4 cA[NMAX];
    __shared__ float4 cB[NMAX];
    __shared__ float2 cC[NMAX];
    __shared__ int    warpCnt[ROUNDS * 4];

    const int tid  = threadIdx.x;
    const int warp = tid >> 5;
    const int lane = tid & 31;
    const unsigned lanemask = (1u << lane) - 1u;

    const int W = *wptr;
    const int H = pixels / W;
    const int tilesX = (W + TW - 1) / TW;
    const int tilesY = (H + TH - 1) / TH;
    const int tileCount = tilesX * tilesY;

    for (int t = blockIdx.x; t < tileCount; t += gridDim.x) {
        int tx = t % tilesX;
        int ty = t / tilesX;
        int x0 = tx * TW;
        int y0 = ty * TH;

        int pxI = x0 + (tid & (TW - 1));
        int pyI = y0 + (tid / TW);
        bool inb = (pxI < W) && (pyI < H);
        float px = (float)pxI + 0.5f;
        float py = (float)pyI + 0.5f;

        float xlo = (float)x0, xhi = (float)(x0 + TW);
        float ylo = (float)y0, yhi = (float)(y0 + TH);

        // ---- cull: 8 ballot rounds, no inter-round barriers ----
        unsigned ball[ROUNDS];
        unsigned predMask = 0;
        #pragma unroll
        for (int r = 0; r < ROUNDS; r++) {
            int gi = r * BT + tid;
            bool pred = false;
            if (gi < N) {
                float4 D = g_D[gi];
                pred = (D.y >= xlo) && (D.x <= xhi) && (D.w >= ylo) && (D.z <= yhi);
            }
            ball[r] = __ballot_sync(0xffffffffu, pred);
            predMask |= pred ? (1u << r) : 0u;
            if (lane == 0) warpCnt[r * 4 + warp] = __popc(ball[r]);
        }
        __syncthreads();

        int wb[ROUNDS];
        int rb = 0;
        #pragma unroll
        for (int r = 0; r < ROUNDS; r++) {
            int c0 = warpCnt[r * 4 + 0], c1 = warpCnt[r * 4 + 1];
            int c2 = warpCnt[r * 4 + 2], c3 = warpCnt[r * 4 + 3];
            int wbase = rb;
            if (warp > 0) wbase += c0;
            if (warp > 1) wbase += c1;
            if (warp > 2) wbase += c2;
            wb[r] = wbase;
            rb += c0 + c1 + c2 + c3;
        }
        const int total = rb;

        #pragma unroll
        for (int r = 0; r < ROUNDS; r++) {
            if (predMask & (1u << r)) {
                int gi = r * BT + tid;
                int off = wb[r] + __popc(ball[r] & lanemask);
                cA[off] = g_A[gi];
                cB[off] = g_B[gi];
                cC[off] = g_C[gi];
            }
        }
        __syncthreads();

        // ---- composite: barrier-free, warp-uniform early exit ----
        float T = 1.0f;
        float r_ = 0.f, g = 0.f, b = 0.f, accW = 0.f, accD = 0.f;
        bool live = inb;

        for (int j = 0; j < total; j++) {
            if (__all_sync(0xffffffffu, !live)) break;
            if (live) {
                float4 Aa = cA[j];
                float dx = px - Aa.x;
                float dy = py - Aa.y;
                float4 Bb = cB[j];
                float sigma = 0.5f * (Aa.z * dx * dx + Bb.x * dy * dy) + Aa.w * dx * dy;
                if (sigma >= 0.f && sigma <= 5.55f) {
                    float alpha = fminf(Bb.y * __expf(-sigma), 0.999f);
                    if (alpha >= (1.0f / 255.0f)) {
                        float w = alpha * T;
                        r_ += w * Bb.z;
                        g  += w * Bb.w;
                        float2 Cc = cC[j];
                        b    += w * Cc.x;
                        accD += w * Cc.y;
                        accW += w;
                        T *= (1.0f - alpha);
                        if (T < 1e-5f) live = false;
                    }
                }
            }
        }

        if (inb) {
            int p = pyI * W + pxI;
            float ed = accD / fmaxf(accW, 1e-10f);
            ((float4*)out)[p] = make_float4(r_, g, b, ed);
            out[pixels * 4 + p] = accW;
        }
        __syncthreads();   // protect smem reuse across grid-stride tiles
    }
}

extern "C" void kernel_launch(void* const* d_in, const int* in_sizes, int n_in,
                              void* d_out, int out_size) {
    const float* means3d = (const float*)d_in[0];
    const float* quats   = (const float*)d_in[1];
    const float* scales  = (const float*)d_in[2];
    const float* opac    = (const float*)d_in[3];
    const float* sh      = (const float*)d_in[4];
    const float* c2w     = (const float*)d_in[5];
    const float* Ks      = (const float*)d_in[6];
    const int*   wptr    = (const int*)d_in[7];
    float* out = (float*)d_out;

    int N = in_sizes[0] / 3;
    if (N > NMAX) N = NMAX;
    int pixels = out_size / 5;

    // one 8-CTA cluster covers all NMAX gaussians
    preprocess_rank_kernel<<<8, 128>>>(means3d, quats, scales, opac, sh, c2w, Ks, N);

    int blocks = (pixels + BT - 1) / BT;
    if (blocks < 1) blocks = 1;
    render_kernel<<<blocks, BT>>>(wptr, out, N, pixels);
}

// round 12
// speedup vs baseline: 4.5135x; 1.2576x over previous
#include <cuda_runtime.h>
#include <math.h>

#define NMAX   1024
#define TW     16
#define TH     8
#define RT     256            // render threads per block (2 per pixel)
#define PIX    128            // pixels per tile
#define ROUNDS (NMAX / RT)    // 4 cull rounds

static __device__ __forceinline__ float finf() { return __int_as_float(0x7f800000); }

// Sorted (render-ready) SoA
__device__ float4 g_A[NMAX]; // mx, my, conA, conB
__device__ float4 g_B[NMAX]; // conC, op, colR, colG
__device__ float2 g_C[NMAX]; // colB, depth
__device__ float4 g_D[NMAX]; // xmin, xmax, ymin, ymax (screen AABB; culled => empty box)
// Key exchange buffer (only 4B/gaussian crosses CTAs)
__device__ float  k_buf[NMAX];

// ---------------------------------------------------------------------------
// Fused preprocess + stable rank-sort + scatter (8-CTA cluster).
// ---------------------------------------------------------------------------
__global__ __launch_bounds__(128) __cluster_dims__(8, 1, 1)
void preprocess_rank_kernel(
    const float* __restrict__ means3d,   // [N,3]
    const float* __restrict__ quats,     // [N,4]
    const float* __restrict__ scales,    // [N,3]
    const float* __restrict__ opac,      // [N]
    const float* __restrict__ sh,        // [N,4,3]
    const float* __restrict__ c2w,       // [4,4]
    const float* __restrict__ Ks,        // [3,3]
    int N)
{
    const float SH_C0 = 0.28209479177387814f;
    const float SH_C1 = 0.4886025119029199f;
    const float NEARP = 0.01f;
    const float FARP  = 1e10f;
    const float LOWPASS = 0.3f;

    __shared__ float skey[NMAX];

    int i = blockIdx.x * blockDim.x + threadIdx.x;   // 0..1023

    float4 oA, oB, oD;
    float2 oC;
    float  key = finf();

    if (i < N) {
        const float4 q4  = *(const float4*)(quats + i * 4);
        const float4 sh0 = *(const float4*)(sh + i * 12);
        const float4 sh1 = *(const float4*)(sh + i * 12 + 4);
        const float4 sh2 = *(const float4*)(sh + i * 12 + 8);
        float m0 = means3d[i * 3 + 0], m1 = means3d[i * 3 + 1], m2 = means3d[i * 3 + 2];
        float s0 = scales[i * 3 + 0], s1 = scales[i * 3 + 1], s2v = scales[i * 3 + 2];
        float opraw = opac[i];

        float Rw[3][3];
        #pragma unroll
        for (int r = 0; r < 3; r++)
            #pragma unroll
            for (int c = 0; c < 3; c++)
                Rw[r][c] = c2w[c * 4 + r];
        float ct0 = c2w[3], ct1 = c2w[7], ct2 = c2w[11];
        float tw[3];
        #pragma unroll
        for (int r = 0; r < 3; r++)
            tw[r] = -(Rw[r][0] * ct0 + Rw[r][1] * ct1 + Rw[r][2] * ct2);

        float fx = Ks[0], cx = Ks[2], fy = Ks[4], cy = Ks[5];

        float x = Rw[0][0] * m0 + Rw[0][1] * m1 + Rw[0][2] * m2 + tw[0];
        float y = Rw[1][0] * m0 + Rw[1][1] * m1 + Rw[1][2] * m2 + tw[1];
        float z = Rw[2][0] * m0 + Rw[2][1] * m1 + Rw[2][2] * m2 + tw[2];

        bool valid = (z > NEARP) && (z < FARP);
        float zs = valid ? z : 1.0f;
        float m2x = fx * x / zs + cx;
        float m2y = fy * y / zs + cy;

        float qw = q4.x, qx = q4.y, qy = q4.z, qz = q4.w;
        float qn = rsqrtf(qw * qw + qx * qx + qy * qy + qz * qz);
        qw *= qn; qx *= qn; qy *= qn; qz *= qn;
        float Rg[3][3];
        Rg[0][0] = 1.f - 2.f * (qy * qy + qz * qz);
        Rg[0][1] = 2.f * (qx * qy - qw * qz);
        Rg[0][2] = 2.f * (qx * qz + qw * qy);
        Rg[1][0] = 2.f * (qx * qy + qw * qz);
        Rg[1][1] = 1.f - 2.f * (qx * qx + qz * qz);
        Rg[1][2] = 2.f * (qy * qz - qw * qx);
        Rg[2][0] = 2.f * (qx * qz - qw * qy);
        Rg[2][1] = 2.f * (qy * qz + qw * qx);
        Rg[2][2] = 1.f - 2.f * (qx * qx + qy * qy);

        float sq[3] = { s0 * s0, s1 * s1, s2v * s2v };

        float cov3[3][3];
        #pragma unroll
        for (int r = 0; r < 3; r++)
            #pragma unroll
            for (int c = 0; c < 3; c++)
                cov3[r][c] = Rg[r][0] * Rg[c][0] * sq[0]
                           + Rg[r][1] * Rg[c][1] * sq[1]
                           + Rg[r][2] * Rg[c][2] * sq[2];

        float Vc[3][3];
        #pragma unroll
        for (int r = 0; r < 3; r++)
            #pragma unroll
            for (int c = 0; c < 3; c++)
                Vc[r][c] = Rw[r][0] * cov3[0][c] + Rw[r][1] * cov3[1][c] + Rw[r][2] * cov3[2][c];
        float cc[3][3];
        #pragma unroll
        for (int r = 0; r < 3; r++)
            #pragma unroll
            for (int c = 0; c < 3; c++)
                cc[r][c] = Vc[r][0] * Rw[c][0] + Vc[r][1] * Rw[c][1] + Vc[r][2] * Rw[c][2];

        float j00 = fx / zs, j02 = -fx * x / (zs * zs);
        float j11 = fy / zs, j12 = -fy * y / (zs * zs);
        float a = j00 * (cc[0][0] * j00 + cc[0][2] * j02)
                + j02 * (cc[2][0] * j00 + cc[2][2] * j02);
        float b = j00 * (cc[0][1] * j11 + cc[0][2] * j12)
                + j02 * (cc[2][1] * j11 + cc[2][2] * j12);
        float c = j11 * (cc[1][1] * j11 + cc[1][2] * j12)
                + j12 * (cc[2][1] * j11 + cc[2][2] * j12);
        a += LOWPASS;
        c += LOWPASS;
        float det = a * c - b * b;
        valid = valid && (det > 0.f);
        float dets = (det > 0.f) ? det : 1.0f;
        float conA = c / dets, conB = -b / dets, conC = a / dets;

        float dx3 = m0 - ct0, dy3 = m1 - ct1, dz3 = m2 - ct2;
        float dn = sqrtf(dx3 * dx3 + dy3 * dy3 + dz3 * dz3);
        dn = fmaxf(dn, 1e-8f);
        float dxn = dx3 / dn, dyn = dy3 / dn, dzn = dz3 / dn;
        float shv[12] = { sh0.x, sh0.y, sh0.z, sh0.w, sh1.x, sh1.y, sh1.z, sh1.w,
                          sh2.x, sh2.y, sh2.z, sh2.w };
        float col[3];
        #pragma unroll
        for (int ch = 0; ch < 3; ch++) {
            float v = SH_C0 * shv[ch]
                    - SH_C1 * dyn * shv[3 + ch]
                    + SH_C1 * dzn * shv[6 + ch]
                    - SH_C1 * dxn * shv[9 + ch];
            col[ch] = fmaxf(v + 0.5f, 0.0f);
        }

        float op = 1.0f / (1.0f + __expf(-opraw));
        op = valid ? op : 0.0f;

        float xmin = 1e30f, xmax = -1e30f, ymin = 1e30f, ymax = -1e30f;
        if (valid && op * 255.f > 1.0f) {
            float sg = fminf(5.55f, logf(255.f * op));
            float rx = sqrtf(2.f * sg * a);
            float ry = sqrtf(2.f * sg * c);
            xmin = m2x - rx; xmax = m2x + rx;
            ymin = m2y - ry; ymax = m2y + ry;
        } else {
            op = 0.f;
        }

        oA = make_float4(m2x, m2y, conA, conB);
        oB = make_float4(conC, op, col[0], col[1]);
        oC = make_float2(col[2], z);
        oD = make_float4(xmin, xmax, ymin, ymax);
        key = (valid && op > 0.f) ? z : finf();
    } else {
        oA = make_float4(0.f, 0.f, 1.f, 0.f);
        oB = make_float4(1.f, 0.f, 0.f, 0.f);
        oC = make_float2(0.f, 0.f);
        oD = make_float4(1e30f, -1e30f, 1e30f, -1e30f);
    }

    k_buf[i] = key;
    __threadfence();
    asm volatile("barrier.cluster.arrive.aligned;" ::: "memory");
    asm volatile("barrier.cluster.wait.aligned;" ::: "memory");

    {
        float4* sk4 = (float4*)skey;
        const float4* kb4 = (const float4*)k_buf;
        int t = threadIdx.x;
        sk4[t]       = kb4[t];
        sk4[t + 128] = kb4[t + 128];
    }
    __syncthreads();

    int rank = 0;
    {
        const float4* sk4 = (const float4*)skey;
        #pragma unroll 4
        for (int j4 = 0; j4 < NMAX / 4; j4++) {
            float4 k = sk4[j4];
            int j = j4 * 4;
            rank += (k.x < key) || ((k.x == key) && (j + 0 < i));
            rank += (k.y < key) || ((k.y == key) && (j + 1 < i));
            rank += (k.z < key) || ((k.z == key) && (j + 2 < i));
            rank += (k.w < key) || ((k.w == key) && (j + 3 < i));
        }
    }

    g_A[rank] = oA;
    g_B[rank] = oB;
    g_C[rank] = oC;
    g_D[rank] = oD;
}

// ---------------------------------------------------------------------------
// Tile render: 256 threads, 2 threads per pixel (split-transmittance),
// branchless unrolled composite. Combine uses DEDICATED smem buffers so it
// never aliases the survivor list (round-11 race fix).
// ---------------------------------------------------------------------------
__global__ __launch_bounds__(RT) void render_kernel(
    const int* __restrict__ wptr,
    float* __restrict__ out,
    int N, int pixels)
{
    __shared__ float4 cA[NMAX];
    __shared__ float4 cB[NMAX];
    __shared__ float2 cC[NMAX];
    __shared__ float4 hA[PIX];     // back-half partial: r,g,b,accW
    __shared__ float2 hC[PIX];     // back-half partial: accD, T_back(unused by front)
    __shared__ int    warpCnt[ROUNDS * 8];

    const int tid  = threadIdx.x;
    const int warp = tid >> 5;
    const int lane = tid & 31;
    const unsigned lanemask = (1u << lane) - 1u;
    const int pid  = tid & (PIX - 1);    // pixel within tile
    const int half = tid >> 7;           // 0 = front list half, 1 = back half

    const int W = *wptr;
    const int H = pixels / W;
    const int tilesX = (W + TW - 1) / TW;
    const int tilesY = (H + TH - 1) / TH;
    const int tileCount = tilesX * tilesY;

    for (int t = blockIdx.x; t < tileCount; t += gridDim.x) {
        int tx = t % tilesX;
        int ty = t / tilesX;
        int x0 = tx * TW;
        int y0 = ty * TH;

        int pxI = x0 + (pid & (TW - 1));
        int pyI = y0 + (pid / TW);
        bool inb = (pxI < W) && (pyI < H);
        float px = (float)pxI + 0.5f;
        float py = (float)pyI + 0.5f;

        float xlo = (float)x0, xhi = (float)(x0 + TW);
        float ylo = (float)y0, yhi = (float)(y0 + TH);

        // ---- cull: 4 ballot rounds over 256 threads ----
        unsigned ball[ROUNDS];
        unsigned predMask = 0;
        #pragma unroll
        for (int r = 0; r < ROUNDS; r++) {
            int gi = r * RT + tid;
            bool pred = false;
            if (gi < N) {
                float4 D = g_D[gi];
                pred = (D.y >= xlo) && (D.x <= xhi) && (D.w >= ylo) && (D.z <= yhi);
            }
            ball[r] = __ballot_sync(0xffffffffu, pred);
            predMask |= pred ? (1u << r) : 0u;
            if (lane == 0) warpCnt[r * 8 + warp] = __popc(ball[r]);
        }
        __syncthreads();

        int wb[ROUNDS];
        int rb = 0;
        #pragma unroll
        for (int r = 0; r < ROUNDS; r++) {
            int wbase = rb;
            #pragma unroll
            for (int w2 = 0; w2 < 8; w2++) {
                int cw = warpCnt[r * 8 + w2];
                if (w2 < warp) wbase += cw;
                rb += cw;
            }
            wb[r] = wbase;
        }
        const int total = rb;

        #pragma unroll
        for (int r = 0; r < ROUNDS; r++) {
            if (predMask & (1u << r)) {
                int gi = r * RT + tid;
                int off = wb[r] + __popc(ball[r] & lanemask);
                cA[off] = g_A[gi];
                cB[off] = g_B[gi];
                cC[off] = g_C[gi];
            }
        }
        __syncthreads();

        // ---- composite: split-T, branchless, 2x unrolled ----
        const int mid  = (total + 1) >> 1;
        const int jbeg = half ? mid : 0;
        const int jend = half ? total : mid;

        float T = 1.0f;
        float r_ = 0.f, g = 0.f, b = 0.f, accW = 0.f, accD = 0.f;

        int j = jbeg;
        for (; j + 1 < jend; j += 2) {
            if (__all_sync(0xffffffffu, T < 1e-5f)) break;
            float4 A0 = cA[j],     A1 = cA[j + 1];
            float4 B0 = cB[j],     B1 = cB[j + 1];
            float dx0 = px - A0.x, dy0 = py - A0.y;
            float dx1 = px - A1.x, dy1 = py - A1.y;
            float s0 = 0.5f * (A0.z * dx0 * dx0 + B0.x * dy0 * dy0) + A0.w * dx0 * dy0;
            float s1 = 0.5f * (A1.z * dx1 * dx1 + B1.x * dy1 * dy1) + A1.w * dx1 * dy1;
            float a0 = fminf(B0.y * __expf(-s0), 0.999f);
            float a1 = fminf(B1.y * __expf(-s1), 0.999f);
            a0 = (s0 >= 0.f && s0 <= 5.55f && a0 >= (1.f / 255.f)) ? a0 : 0.f;
            a1 = (s1 >= 0.f && s1 <= 5.55f && a1 >= (1.f / 255.f)) ? a1 : 0.f;
            float2 C0 = cC[j], C1 = cC[j + 1];
            float w0 = a0 * T;
            r_ += w0 * B0.z; g += w0 * B0.w; b += w0 * C0.x;
            accD += w0 * C0.y; accW += w0;
            T *= (1.0f - a0);
            float w1 = a1 * T;
            r_ += w1 * B1.z; g += w1 * B1.w; b += w1 * C1.x;
            accD += w1 * C1.y; accW += w1;
            T *= (1.0f - a1);
        }
        if (j < jend && !(T < 1e-5f)) {
            float4 A0 = cA[j];
            float4 B0 = cB[j];
            float dx0 = px - A0.x, dy0 = py - A0.y;
            float s0 = 0.5f * (A0.z * dx0 * dx0 + B0.x * dy0 * dy0) + A0.w * dx0 * dy0;
            float a0 = fminf(B0.y * __expf(-s0), 0.999f);
            a0 = (s0 >= 0.f && s0 <= 5.55f && a0 >= (1.f / 255.f)) ? a0 : 0.f;
            float2 C0 = cC[j];
            float w0 = a0 * T;
            r_ += w0 * B0.z; g += w0 * B0.w; b += w0 * C0.x;
            accD += w0 * C0.y; accW += w0;
            T *= (1.0f - a0);
        }

        // ---- combine halves via dedicated buffers: result = front + T_front*back ----
        if (half == 1) {
            hA[pid] = make_float4(r_, g, b, accW);
            hC[pid] = make_float2(accD, T);
        }
        __syncthreads();
        if (half == 0 && inb) {
            float4 h1 = hA[pid];
            float2 h1c = hC[pid];
            r_   += T * h1.x;
            g    += T * h1.y;
            b    += T * h1.z;
            accW += T * h1.w;
            accD += T * h1c.x;
            int p = pyI * W + pxI;
            float ed = accD / fmaxf(accW, 1e-10f);
            ((float4*)out)[p] = make_float4(r_, g, b, ed);
            out[pixels * 4 + p] = accW;
        }
        __syncthreads();   // protect smem reuse across grid-stride tiles
    }
}

extern "C" void kernel_launch(void* const* d_in, const int* in_sizes, int n_in,
                              void* d_out, int out_size) {
    const float* means3d = (const float*)d_in[0];
    const float* quats   = (const float*)d_in[1];
    const float* scales  = (const float*)d_in[2];
    const float* opac    = (const float*)d_in[3];
    const float* sh      = (const float*)d_in[4];
    const float* c2w     = (const float*)d_in[5];
    const float* Ks      = (const float*)d_in[6];
    const int*   wptr    = (const int*)d_in[7];
    float* out = (float*)d_out;

    int N = in_sizes[0] / 3;
    if (N > NMAX) N = NMAX;
    int pixels = out_size / 5;

    preprocess_rank_kernel<<<8, 128>>>(means3d, quats, scales, opac, sh, c2w, Ks, N);

    int blocks = (pixels + PIX - 1) / PIX;
    if (blocks < 1) blocks = 1;
    render_kernel<<<blocks, RT>>>(wptr, out, N, pixels);
}

// round 13
// speedup vs baseline: 4.7634x; 1.0554x over previous
#include <cuda_runtime.h>
#include <math.h>

#define NMAX   1024
#define TW     16
#define TH     8
#define RT     512            // render threads per block (4 per pixel)
#define PIX    128            // pixels per tile
#define ROUNDS (NMAX / RT)    // 2 cull rounds

static __device__ __forceinline__ float finf() { return __int_as_float(0x7f800000); }

// Sorted (render-ready) SoA
__device__ float4 g_A[NMAX]; // mx, my, conA, conB
__device__ float4 g_B[NMAX]; // conC, op, colR, colG
__device__ float2 g_C[NMAX]; // colB, depth
__device__ float4 g_D[NMAX]; // xmin, xmax, ymin, ymax (screen AABB; culled => empty box)
// Key exchange buffer (only 4B/gaussian crosses CTAs)
__device__ float  k_buf[NMAX];

// ---------------------------------------------------------------------------
// Fused preprocess + stable rank-sort + scatter (8-CTA cluster, 256 thr/CTA).
// Lower 128 threads/CTA: full math for one gaussian (payload in registers) +
// rank over keys [0,512). Upper 128 threads: rank over keys [512,1024).
// ---------------------------------------------------------------------------
__global__ __launch_bounds__(256) __cluster_dims__(8, 1, 1)
void preprocess_rank_kernel(
    const float* __restrict__ means3d,   // [N,3]
    const float* __restrict__ quats,     // [N,4]
    const float* __restrict__ scales,    // [N,3]
    const float* __restrict__ opac,      // [N]
    const float* __restrict__ sh,        // [N,4,3]
    const float* __restrict__ c2w,       // [4,4]
    const float* __restrict__ Ks,        // [3,3]
    int N)
{
    const float SH_C0 = 0.28209479177387814f;
    const float SH_C1 = 0.4886025119029199f;
    const float NEARP = 0.01f;
    const float FARP  = 1e10f;
    const float LOWPASS = 0.3f;

    __shared__ float skey[NMAX];
    __shared__ int   rp[128];   // upper-half partial ranks

    const int il   = threadIdx.x & 127;      // gaussian slot within CTA
    const int hi   = threadIdx.x >> 7;       // 0 = math+low rank, 1 = high rank
    const int i    = blockIdx.x * 128 + il;  // gaussian index 0..1023

    float4 oA, oB, oD;
    float2 oC;
    float  key = finf();

    if (hi == 0 && i < N) {
        const float4 q4  = *(const float4*)(quats + i * 4);
        const float4 sh0 = *(const float4*)(sh + i * 12);
        const float4 sh1 = *(const float4*)(sh + i * 12 + 4);
        const float4 sh2 = *(const float4*)(sh + i * 12 + 8);
        float m0 = means3d[i * 3 + 0], m1 = means3d[i * 3 + 1], m2 = means3d[i * 3 + 2];
        float s0 = scales[i * 3 + 0], s1 = scales[i * 3 + 1], s2v = scales[i * 3 + 2];
        float opraw = opac[i];

        float Rw[3][3];
        #pragma unroll
        for (int r = 0; r < 3; r++)
            #pragma unroll
            for (int c = 0; c < 3; c++)
                Rw[r][c] = c2w[c * 4 + r];
        float ct0 = c2w[3], ct1 = c2w[7], ct2 = c2w[11];
        float tw[3];
        #pragma unroll
        for (int r = 0; r < 3; r++)
            tw[r] = -(Rw[r][0] * ct0 + Rw[r][1] * ct1 + Rw[r][2] * ct2);

        float fx = Ks[0], cx = Ks[2], fy = Ks[4], cy = Ks[5];

        float x = Rw[0][0] * m0 + Rw[0][1] * m1 + Rw[0][2] * m2 + tw[0];
        float y = Rw[1][0] * m0 + Rw[1][1] * m1 + Rw[1][2] * m2 + tw[1];
        float z = Rw[2][0] * m0 + Rw[2][1] * m1 + Rw[2][2] * m2 + tw[2];

        bool valid = (z > NEARP) && (z < FARP);
        float zs = valid ? z : 1.0f;
        float m2x = fx * x / zs + cx;
        float m2y = fy * y / zs + cy;

        float qw = q4.x, qx = q4.y, qy = q4.z, qz = q4.w;
        float qn = rsqrtf(qw * qw + qx * qx + qy * qy + qz * qz);
        qw *= qn; qx *= qn; qy *= qn; qz *= qn;
        float Rg[3][3];
        Rg[0][0] = 1.f - 2.f * (qy * qy + qz * qz);
        Rg[0][1] = 2.f * (qx * qy - qw * qz);
        Rg[0][2] = 2.f * (qx * qz + qw * qy);
        Rg[1][0] = 2.f * (qx * qy + qw * qz);
        Rg[1][1] = 1.f - 2.f * (qx * qx + qz * qz);
        Rg[1][2] = 2.f * (qy * qz - qw * qx);
        Rg[2][0] = 2.f * (qx * qz - qw * qy);
        Rg[2][1] = 2.f * (qy * qz + qw * qx);
        Rg[2][2] = 1.f - 2.f * (qx * qx + qy * qy);

        float sq[3] = { s0 * s0, s1 * s1, s2v * s2v };

        float cov3[3][3];
        #pragma unroll
        for (int r = 0; r < 3; r++)
            #pragma unroll
            for (int c = 0; c < 3; c++)
                cov3[r][c] = Rg[r][0] * Rg[c][0] * sq[0]
                           + Rg[r][1] * Rg[c][1] * sq[1]
                           + Rg[r][2] * Rg[c][2] * sq[2];

        float Vc[3][3];
        #pragma unroll
        for (int r = 0; r < 3; r++)
            #pragma unroll
            for (int c = 0; c < 3; c++)
                Vc[r][c] = Rw[r][0] * cov3[0][c] + Rw[r][1] * cov3[1][c] + Rw[r][2] * cov3[2][c];
        float cc[3][3];
        #pragma unroll
        for (int r = 0; r < 3; r++)
            #pragma unroll
            for (int c = 0; c < 3; c++)
                cc[r][c] = Vc[r][0] * Rw[c][0] + Vc[r][1] * Rw[c][1] + Vc[r][2] * Rw[c][2];

        float j00 = fx / zs, j02 = -fx * x / (zs * zs);
        float j11 = fy / zs, j12 = -fy * y / (zs * zs);
        float a = j00 * (cc[0][0] * j00 + cc[0][2] * j02)
                + j02 * (cc[2][0] * j00 + cc[2][2] * j02);
        float b = j00 * (cc[0][1] * j11 + cc[0][2] * j12)
                + j02 * (cc[2][1] * j11 + cc[2][2] * j12);
        float c = j11 * (cc[1][1] * j11 + cc[1][2] * j12)
                + j12 * (cc[2][1] * j11 + cc[2][2] * j12);
        a += LOWPASS;
        c += LOWPASS;
        float det = a * c - b * b;
        valid = valid && (det > 0.f);
        float dets = (det > 0.f) ? det : 1.0f;
        float conA = c / dets, conB = -b / dets, conC = a / dets;

        float dx3 = m0 - ct0, dy3 = m1 - ct1, dz3 = m2 - ct2;
        float dn = sqrtf(dx3 * dx3 + dy3 * dy3 + dz3 * dz3);
        dn = fmaxf(dn, 1e-8f);
        float dxn = dx3 / dn, dyn = dy3 / dn, dzn = dz3 / dn;
        float shv[12] = { sh0.x, sh0.y, sh0.z, sh0.w, sh1.x, sh1.y, sh1.z, sh1.w,
                          sh2.x, sh2.y, sh2.z, sh2.w };
        float col[3];
        #pragma unroll
        for (int ch = 0; ch < 3; ch++) {
            float v = SH_C0 * shv[ch]
                    - SH_C1 * dyn * shv[3 + ch]
                    + SH_C1 * dzn * shv[6 + ch]
                    - SH_C1 * dxn * shv[9 + ch];
            col[ch] = fmaxf(v + 0.5f, 0.0f);
        }

        float op = 1.0f / (1.0f + __expf(-opraw));
        op = valid ? op : 0.0f;

        float xmin = 1e30f, xmax = -1e30f, ymin = 1e30f, ymax = -1e30f;
        if (valid && op * 255.f > 1.0f) {
            float sg = fminf(5.55f, logf(255.f * op));
            float rx = sqrtf(2.f * sg * a);
            float ry = sqrtf(2.f * sg * c);
            xmin = m2x - rx; xmax = m2x + rx;
            ymin = m2y - ry; ymax = m2y + ry;
        } else {
            op = 0.f;
        }

        oA = make_float4(m2x, m2y, conA, conB);
        oB = make_float4(conC, op, col[0], col[1]);
        oC = make_float2(col[2], z);
        oD = make_float4(xmin, xmax, ymin, ymax);
        key = (valid && op > 0.f) ? z : finf();
    }

    // Publish key (lower half only), fence, cluster sync.
    if (hi == 0) {
        k_buf[i] = key;
        __threadfence();
    }
    asm volatile("barrier.cluster.arrive.aligned;" ::: "memory");
    asm volatile("barrier.cluster.wait.aligned;" ::: "memory");

    // Load all keys into smem (256 threads x 1 float4 each)
    ((float4*)skey)[threadIdx.x] = ((const float4*)k_buf)[threadIdx.x];
    __syncthreads();

    // Split rank: hi=0 covers keys [0,512), hi=1 covers [512,1024).
    float ki = skey[i];
    int rank = 0;
    {
        const float4* sk4 = (const float4*)skey;
        const int base4 = hi * 128;
        #pragma unroll 4
        for (int j4 = 0; j4 < 128; j4++) {
            float4 k = sk4[base4 + j4];
            int j = (base4 + j4) * 4;
            rank += (k.x < ki) || ((k.x == ki) && (j + 0 < i));
            rank += (k.y < ki) || ((k.y == ki) && (j + 1 < i));
            rank += (k.z < ki) || ((k.z == ki) && (j + 2 < i));
            rank += (k.w < ki) || ((k.w == ki) && (j + 3 < i));
        }
    }
    if (hi == 1) rp[il] = rank;
    __syncthreads();

    if (hi == 0 && i < N) {
        rank += rp[il];
        g_A[rank] = oA;
        g_B[rank] = oB;
        g_C[rank] = oC;
        g_D[rank] = oD;
    }
}

// ---------------------------------------------------------------------------
// Tile render: 512 threads, 4 threads per pixel (4-way split-transmittance),
// branchless unrolled composite, dedicated combine buffers.
// ---------------------------------------------------------------------------
__global__ __launch_bounds__(RT) void render_kernel(
    const int* __restrict__ wptr,
    float* __restrict__ out,
    int N, int pixels)
{
    __shared__ float4 cA[NMAX];
    __shared__ float4 cB[NMAX];
    __shared__ float2 cC[NMAX];
    __shared__ float4 pA[3][PIX];   // quarters 1..3 partial: r,g,b,accW
    __shared__ float2 pC[3][PIX];   // quarters 1..3 partial: accD, T
    __shared__ int    warpCnt[ROUNDS * 16];

    const int tid  = threadIdx.x;
    const int warp = tid >> 5;
    const int lane = tid & 31;
    const unsigned lanemask = (1u << lane) - 1u;
    const int pid  = tid & (PIX - 1);    // pixel within tile
    const int qtr  = tid >> 7;           // quarter of the survivor list

    const int W = *wptr;
    const int H = pixels / W;
    const int tilesX = (W + TW - 1) / TW;
    const int tilesY = (H + TH - 1) / TH;
    const int tileCount = tilesX * tilesY;

    for (int t = blockIdx.x; t < tileCount; t += gridDim.x) {
        int tx = t % tilesX;
        int ty = t / tilesX;
        int x0 = tx * TW;
        int y0 = ty * TH;

        int pxI = x0 + (pid & (TW - 1));
        int pyI = y0 + (pid / TW);
        bool inb = (pxI < W) && (pyI < H);
        float px = (float)pxI + 0.5f;
        float py = (float)pyI + 0.5f;

        float xlo = (float)x0, xhi = (float)(x0 + TW);
        float ylo = (float)y0, yhi = (float)(y0 + TH);

        // ---- cull: 2 ballot rounds over 512 threads ----
        unsigned ball[ROUNDS];
        unsigned predMask = 0;
        #pragma unroll
        for (int r = 0; r < ROUNDS; r++) {
            int gi = r * RT + tid;
            bool pred = false;
            if (gi < N) {
                float4 D = g_D[gi];
                pred = (D.y >= xlo) && (D.x <= xhi) && (D.w >= ylo) && (D.z <= yhi);
            }
            ball[r] = __ballot_sync(0xffffffffu, pred);
            predMask |= pred ? (1u << r) : 0u;
            if (lane == 0) warpCnt[r * 16 + warp] = __popc(ball[r]);
        }
        __syncthreads();

        int wb[ROUNDS];
        int rb = 0;
        #pragma unroll
        for (int r = 0; r < ROUNDS; r++) {
            int wbase = rb;
            #pragma unroll
            for (int w2 = 0; w2 < 16; w2++) {
                int cw = warpCnt[r * 16 + w2];
                if (w2 < warp) wbase += cw;
                rb += cw;
            }
            wb[r] = wbase;
        }
        const int total = rb;

        #pragma unroll
        for (int r = 0; r < ROUNDS; r++) {
            if (predMask & (1u << r)) {
                int gi = r * RT + tid;
                int off = wb[r] + __popc(ball[r] & lanemask);
                cA[off] = g_A[gi];
                cB[off] = g_B[gi];
                cC[off] = g_C[gi];
            }
        }
        __syncthreads();

        // ---- composite: 4-way split-T, branchless, 2x unrolled ----
        const int s    = (total + 3) >> 2;
        int jbeg = qtr * s;       if (jbeg > total) jbeg = total;
        int jend = jbeg + s;      if (jend > total) jend = total;

        float T = 1.0f;
        float r_ = 0.f, g = 0.f, b = 0.f, accW = 0.f, accD = 0.f;

        int j = jbeg;
        for (; j + 1 < jend; j += 2) {
            if (__all_sync(0xffffffffu, T < 1e-5f)) break;
            float4 A0 = cA[j],     A1 = cA[j + 1];
            float4 B0 = cB[j],     B1 = cB[j + 1];
            float dx0 = px - A0.x, dy0 = py - A0.y;
            float dx1 = px - A1.x, dy1 = py - A1.y;
            float s0 = 0.5f * (A0.z * dx0 * dx0 + B0.x * dy0 * dy0) + A0.w * dx0 * dy0;
            float s1 = 0.5f * (A1.z * dx1 * dx1 + B1.x * dy1 * dy1) + A1.w * dx1 * dy1;
            float a0 = fminf(B0.y * __expf(-s0), 0.999f);
            float a1 = fminf(B1.y * __expf(-s1), 0.999f);
            a0 = (s0 >= 0.f && s0 <= 5.55f && a0 >= (1.f / 255.f)) ? a0 : 0.f;
            a1 = (s1 >= 0.f && s1 <= 5.55f && a1 >= (1.f / 255.f)) ? a1 : 0.f;
            float2 C0 = cC[j], C1 = cC[j + 1];
            float w0 = a0 * T;
            r_ += w0 * B0.z; g += w0 * B0.w; b += w0 * C0.x;
            accD += w0 * C0.y; accW += w0;
            T *= (1.0f - a0);
            float w1 = a1 * T;
            r_ += w1 * B1.z; g += w1 * B1.w; b += w1 * C1.x;
            accD += w1 * C1.y; accW += w1;
            T *= (1.0f - a1);
        }
        if (j < jend && !(T < 1e-5f)) {
            float4 A0 = cA[j];
            float4 B0 = cB[j];
            float dx0 = px - A0.x, dy0 = py - A0.y;
            float s0 = 0.5f * (A0.z * dx0 * dx0 + B0.x * dy0 * dy0) + A0.w * dx0 * dy0;
            float a0 = fminf(B0.y * __expf(-s0), 0.999f);
            a0 = (s0 >= 0.f && s0 <= 5.55f && a0 >= (1.f / 255.f)) ? a0 : 0.f;
            float2 C0 = cC[j];
            float w0 = a0 * T;
            r_ += w0 * B0.z; g += w0 * B0.w; b += w0 * C0.x;
            accD += w0 * C0.y; accW += w0;
            T *= (1.0f - a0);
        }

        // ---- combine: res = p0 + T0*p1 + T0*T1*p2 + T0*T1*T2*p3 ----
        if (qtr > 0) {
            pA[qtr - 1][pid] = make_float4(r_, g, b, accW);
            pC[qtr - 1][pid] = make_float2(accD, T);
        }
        __syncthreads();
        if (qtr == 0 && inb) {
            float4 P1 = pA[0][pid], P2 = pA[1][pid], P3 = pA[2][pid];
            float2 Q1 = pC[0][pid], Q2 = pC[1][pid], Q3 = pC[2][pid];
            float t01  = T * Q1.y;       // T0*T1
            float t012 = t01 * Q2.y;     // T0*T1*T2
            r_   += T * P1.x + t01 * P2.x + t012 * P3.x;
            g    += T * P1.y + t01 * P2.y + t012 * P3.y;
            b    += T * P1.z + t01 * P2.z + t012 * P3.z;
            accW += T * P1.w + t01 * P2.w + t012 * P3.w;
            accD += T * Q1.x + t01 * Q2.x + t012 * Q3.x;
            int p = pyI * W + pxI;
            float ed = accD / fmaxf(accW, 1e-10f);
            ((float4*)out)[p] = make_float4(r_, g, b, ed);
            out[pixels * 4 + p] = accW;
        }
        __syncthreads();   // protect smem reuse across grid-stride tiles
    }
}

extern "C" void kernel_launch(void* const* d_in, const int* in_sizes, int n_in,
                              void* d_out, int out_size) {
    const float* means3d = (const float*)d_in[0];
    const float* quats   = (const float*)d_in[1];
    const float* scales  = (const float*)d_in[2];
    const float* opac    = (const float*)d_in[3];
    const float* sh      = (const float*)d_in[4];
    const float* c2w     = (const float*)d_in[5];
    const float* Ks      = (const float*)d_in[6];
    const int*   wptr    = (const int*)d_in[7];
    float* out = (float*)d_out;

    int N = in_sizes[0] / 3;
    if (N > NMAX) N = NMAX;
    int pixels = out_size / 5;

    preprocess_rank_kernel<<<8, 256>>>(means3d, quats, scales, opac, sh, c2w, Ks, N);

    int blocks = (pixels + PIX - 1) / PIX;
    if (blocks < 1) blocks = 1;
    render_kernel<<<blocks, RT>>>(wptr, out, N, pixels);
}

// round 14
// speedup vs baseline: 6.0148x; 1.2627x over previous
#include <cuda_runtime.h>
#include <math.h>

#define NMAX   1024
#define TW     16
#define TH     8
#define RT     512            // threads per block
#define PIX    128            // pixels per tile
#define ROUNDS (NMAX / RT)    // 2 cull rounds
#define PREB   16             // preprocess blocks
#define GPB    (NMAX / PREB)  // 64 gaussians per preprocess block
#define OPCUT  (-5.53f)       // sigmoid(o) > 1/255  <=>  o > ln(1/254) = -5.5373 (conservative)

static __device__ __forceinline__ float finf() { return __int_as_float(0x7f800000); }

// Sorted (render-ready) SoA
__device__ float4 g_A[NMAX]; // mx, my, conA, conB
__device__ float4 g_B[NMAX]; // conC, op, colR, colG
__device__ float2 g_C[NMAX]; // colB, depth
__device__ float4 g_D[NMAX]; // xmin, xmax, ymin, ymax (screen AABB; culled => empty box)
// Cross-block sync (reset each launch by the last exiting block)
__device__ int g_done = 0;   // # preprocess blocks finished
__device__ int g_exit = 0;   // monotone exit counter (never reset)

__global__ __launch_bounds__(RT, 2) void gs_fused_kernel(
    const float* __restrict__ means3d,   // [N,3]
    const float* __restrict__ quats,     // [N,4]
    const float* __restrict__ scales,    // [N,3]
    const float* __restrict__ opac,      // [N]
    const float* __restrict__ sh,        // [N,4,3]
    const float* __restrict__ c2w,       // [4,4]
    const float* __restrict__ Ks,        // [3,3]
    const int*   __restrict__ wptr,
    float* __restrict__ out,
    int N, int pixels)
{
    __shared__ float4 cA[NMAX];
    __shared__ float4 cB[NMAX];
    __shared__ float2 cC[NMAX];
    __shared__ float4 pA[3][PIX];
    __shared__ float2 pC[3][PIX];
    __shared__ int    warpCnt[ROUNDS * 16];

    const int tid = threadIdx.x;

    if (blockIdx.x < PREB) {
        // ================= PREPROCESS BLOCK =================
        // smem aliases (preprocess blocks never render)
        float* skey = (float*)cA;     // 1024 keys
        int*   pr   = (int*)cB;       // 8 x 64 partial ranks

        const float SH_C0 = 0.28209479177387814f;
        const float SH_C1 = 0.4886025119029199f;
        const float NEARP = 0.01f;
        const float FARP  = 1e10f;
        const float LOWPASS = 0.3f;

        // viewmat = inv(camtoworld) (rigid): Rw = camR^T, tw = -Rw * camt
        float Rw[3][3];
        #pragma unroll
        for (int r = 0; r < 3; r++)
            #pragma unroll
            for (int c = 0; c < 3; c++)
                Rw[r][c] = c2w[c * 4 + r];
        float ct0 = c2w[3], ct1 = c2w[7], ct2 = c2w[11];
        float tw[3];
        #pragma unroll
        for (int r = 0; r < 3; r++)
            tw[r] = -(Rw[r][0] * ct0 + Rw[r][1] * ct1 + Rw[r][2] * ct2);

        float fx = Ks[0], cx = Ks[2], fy = Ks[4], cy = Ks[5];

        // ---- 1) all threads: keys for 2 gaussians each ----
        #pragma unroll
        for (int g = tid; g < NMAX; g += RT) {
            float key = finf();
            if (g < N) {
                float m0 = means3d[g * 3 + 0], m1 = means3d[g * 3 + 1], m2 = means3d[g * 3 + 2];
                float opr = opac[g];
                float z = Rw[2][0] * m0 + Rw[2][1] * m1 + Rw[2][2] * m2 + tw[2];
                if (z > NEARP && z < FARP && opr > OPCUT) key = z;
            }
            skey[g] = key;
        }
        __syncthreads();

        // ---- 2) payload math for this block's GPB gaussians ----
        const int i = blockIdx.x * GPB + (tid & (GPB - 1));  // my gaussian (for rank too)
        float4 oA, oB, oD;
        float2 oC;

        if (tid < GPB && i < N) {
            const float4 q4  = *(const float4*)(quats + i * 4);
            const float4 sh0 = *(const float4*)(sh + i * 12);
            const float4 sh1 = *(const float4*)(sh + i * 12 + 4);
            const float4 sh2 = *(const float4*)(sh + i * 12 + 8);
            float m0 = means3d[i * 3 + 0], m1 = means3d[i * 3 + 1], m2 = means3d[i * 3 + 2];
            float s0 = scales[i * 3 + 0], s1 = scales[i * 3 + 1], s2v = scales[i * 3 + 2];
            float opraw = opac[i];

            float x = Rw[0][0] * m0 + Rw[0][1] * m1 + Rw[0][2] * m2 + tw[0];
            float y = Rw[1][0] * m0 + Rw[1][1] * m1 + Rw[1][2] * m2 + tw[1];
            float z = Rw[2][0] * m0 + Rw[2][1] * m1 + Rw[2][2] * m2 + tw[2];

            bool valid = (z > NEARP) && (z < FARP);
            float zs = valid ? z : 1.0f;
            float m2x = fx * x / zs + cx;
            float m2y = fy * y / zs + cy;

            float qw = q4.x, qx = q4.y, qy = q4.z, qz = q4.w;
            float qn = rsqrtf(qw * qw + qx * qx + qy * qy + qz * qz);
            qw *= qn; qx *= qn; qy *= qn; qz *= qn;
            float Rg[3][3];
            Rg[0][0] = 1.f - 2.f * (qy * qy + qz * qz);
            Rg[0][1] = 2.f * (qx * qy - qw * qz);
            Rg[0][2] = 2.f * (qx * qz + qw * qy);
            Rg[1][0] = 2.f * (qx * qy + qw * qz);
            Rg[1][1] = 1.f - 2.f * (qx * qx + qz * qz);
            Rg[1][2] = 2.f * (qy * qz - qw * qx);
            Rg[2][0] = 2.f * (qx * qz - qw * qy);
            Rg[2][1] = 2.f * (qy * qz + qw * qx);
            Rg[2][2] = 1.f - 2.f * (qx * qx + qy * qy);

            float sq[3] = { s0 * s0, s1 * s1, s2v * s2v };

            float cov3[3][3];
            #pragma unroll
            for (int r = 0; r < 3; r++)
                #pragma unroll
                for (int c = 0; c < 3; c++)
                    cov3[r][c] = Rg[r][0] * Rg[c][0] * sq[0]
                               + Rg[r][1] * Rg[c][1] * sq[1]
                               + Rg[r][2] * Rg[c][2] * sq[2];

            float Vc[3][3];
            #pragma unroll
            for (int r = 0; r < 3; r++)
                #pragma unroll
                for (int c = 0; c < 3; c++)
                    Vc[r][c] = Rw[r][0] * cov3[0][c] + Rw[r][1] * cov3[1][c] + Rw[r][2] * cov3[2][c];
            float cc[3][3];
            #pragma unroll
            for (int r = 0; r < 3; r++)
                #pragma unroll
                for (int c = 0; c < 3; c++)
                    cc[r][c] = Vc[r][0] * Rw[c][0] + Vc[r][1] * Rw[c][1] + Vc[r][2] * Rw[c][2];

            float j00 = fx / zs, j02 = -fx * x / (zs * zs);
            float j11 = fy / zs, j12 = -fy * y / (zs * zs);
            float a = j00 * (cc[0][0] * j00 + cc[0][2] * j02)
                    + j02 * (cc[2][0] * j00 + cc[2][2] * j02);
            float b = j00 * (cc[0][1] * j11 + cc[0][2] * j12)
                    + j02 * (cc[2][1] * j11 + cc[2][2] * j12);
            float c = j11 * (cc[1][1] * j11 + cc[1][2] * j12)
                    + j12 * (cc[2][1] * j11 + cc[2][2] * j12);
            a += LOWPASS;
            c += LOWPASS;
            float det = a * c - b * b;
            valid = valid && (det > 0.f);
            float dets = (det > 0.f) ? det : 1.0f;
            float conA = c / dets, conB = -b / dets, conC = a / dets;

            float dx3 = m0 - ct0, dy3 = m1 - ct1, dz3 = m2 - ct2;
            float dn = sqrtf(dx3 * dx3 + dy3 * dy3 + dz3 * dz3);
            dn = fmaxf(dn, 1e-8f);
            float dxn = dx3 / dn, dyn = dy3 / dn, dzn = dz3 / dn;
            float shv[12] = { sh0.x, sh0.y, sh0.z, sh0.w, sh1.x, sh1.y, sh1.z, sh1.w,
                              sh2.x, sh2.y, sh2.z, sh2.w };
            float col[3];
            #pragma unroll
            for (int ch = 0; ch < 3; ch++) {
                float v = SH_C0 * shv[ch]
                        - SH_C1 * dyn * shv[3 + ch]
                        + SH_C1 * dzn * shv[6 + ch]
                        - SH_C1 * dxn * shv[9 + ch];
                col[ch] = fmaxf(v + 0.5f, 0.0f);
            }

            float op = 1.0f / (1.0f + __expf(-opraw));
            op = valid ? op : 0.0f;

            float xmin = 1e30f, xmax = -1e30f, ymin = 1e30f, ymax = -1e30f;
            if (valid && opraw > OPCUT) {
                float sg = fminf(5.55f, logf(255.f * op));
                float rx = sqrtf(2.f * sg * a);
                float ry = sqrtf(2.f * sg * c);
                xmin = m2x - rx; xmax = m2x + rx;
                ymin = m2y - ry; ymax = m2y + ry;
            } else {
                op = 0.f;
            }

            oA = make_float4(m2x, m2y, conA, conB);
            oB = make_float4(conC, op, col[0], col[1]);
            oC = make_float2(col[2], z);
            oD = make_float4(xmin, xmax, ymin, ymax);
        }

        // ---- 3) 8-way split stable rank of my gaussian vs all keys ----
        {
            const int gl = tid & (GPB - 1);
            const int sl = tid >> 6;                 // 0..7, each slice = 128 keys
            const int ig = blockIdx.x * GPB + gl;
            const float ki = skey[ig];
            int r = 0;
            const float4* sk4 = (const float4*)skey;
            const int b4 = sl * 32;
            #pragma unroll 4
            for (int j4 = 0; j4 < 32; j4++) {
                float4 k = sk4[b4 + j4];
                int j = (b4 + j4) * 4;
                r += (k.x < ki) || ((k.x == ki) && (j + 0 < ig));
                r += (k.y < ki) || ((k.y == ki) && (j + 1 < ig));
                r += (k.z < ki) || ((k.z == ki) && (j + 2 < ig));
                r += (k.w < ki) || ((k.w == ki) && (j + 3 < ig));
            }
            pr[sl * GPB + gl] = r;
        }
        __syncthreads();

        // ---- 4) scatter ----
        if (tid < GPB && i < N) {
            int rank = 0;
            #pragma unroll
            for (int s = 0; s < 8; s++) rank += pr[s * GPB + tid];
            g_A[rank] = oA;
            g_B[rank] = oB;
            g_C[rank] = oC;
            g_D[rank] = oD;
        }
        __threadfence();
        __syncthreads();
        if (tid == 0) atomicAdd(&g_done, 1);
    } else {
        // ================= RENDER BLOCK =================
        if (tid == 0) {
            while (*(volatile int*)&g_done < PREB) __nanosleep(64);
        }
        __syncthreads();
        __threadfence();

        const int warp = tid >> 5;
        const int lane = tid & 31;
        const unsigned lanemask = (1u << lane) - 1u;
        const int pid  = tid & (PIX - 1);
        const int qtr  = tid >> 7;

        const int W = *wptr;
        const int H = pixels / W;
        const int tilesX = (W + TW - 1) / TW;
        const int tilesY = (H + TH - 1) / TH;
        const int tileCount = tilesX * tilesY;
        const int rstride = gridDim.x - PREB;

        for (int t = blockIdx.x - PREB; t < tileCount; t += rstride) {
            int tx = t % tilesX;
            int ty = t / tilesX;
            int x0 = tx * TW;
            int y0 = ty * TH;

            int pxI = x0 + (pid & (TW - 1));
            int pyI = y0 + (pid / TW);
            bool inb = (pxI < W) && (pyI < H);
            float px = (float)pxI + 0.5f;
            float py = (float)pyI + 0.5f;

            float xlo = (float)x0, xhi = (float)(x0 + TW);
            float ylo = (float)y0, yhi = (float)(y0 + TH);

            // ---- cull: 2 ballot rounds over 512 threads ----
            unsigned ball[ROUNDS];
            unsigned predMask = 0;
            #pragma unroll
            for (int r = 0; r < ROUNDS; r++) {
                int gi = r * RT + tid;
                bool pred = false;
                if (gi < N) {
                    float4 D = g_D[gi];
                    pred = (D.y >= xlo) && (D.x <= xhi) && (D.w >= ylo) && (D.z <= yhi);
                }
                ball[r] = __ballot_sync(0xffffffffu, pred);
                predMask |= pred ? (1u << r) : 0u;
                if (lane == 0) warpCnt[r * 16 + warp] = __popc(ball[r]);
            }
            __syncthreads();

            int wb[ROUNDS];
            int rb = 0;
            #pragma unroll
            for (int r = 0; r < ROUNDS; r++) {
                int wbase = rb;
                #pragma unroll
                for (int w2 = 0; w2 < 16; w2++) {
                    int cw = warpCnt[r * 16 + w2];
                    if (w2 < warp) wbase += cw;
                    rb += cw;
                }
                wb[r] = wbase;
            }
            const int total = rb;

            #pragma unroll
            for (int r = 0; r < ROUNDS; r++) {
                if (predMask & (1u << r)) {
                    int gi = r * RT + tid;
                    int off = wb[r] + __popc(ball[r] & lanemask);
                    cA[off] = g_A[gi];
                    cB[off] = g_B[gi];
                    cC[off] = g_C[gi];
                }
            }
            __syncthreads();

            // ---- composite: 4-way split-T, branchless, 2x unrolled ----
            const int s = (total + 3) >> 2;
            int jbeg = qtr * s;  if (jbeg > total) jbeg = total;
            int jend = jbeg + s; if (jend > total) jend = total;

            float T = 1.0f;
            float r_ = 0.f, g = 0.f, b = 0.f, accW = 0.f, accD = 0.f;

            int j = jbeg;
            for (; j + 1 < jend; j += 2) {
                if (__all_sync(0xffffffffu, T < 1e-5f)) break;
                float4 A0 = cA[j],     A1 = cA[j + 1];
                float4 B0 = cB[j],     B1 = cB[j + 1];
                float dx0 = px - A0.x, dy0 = py - A0.y;
                float dx1 = px - A1.x, dy1 = py - A1.y;
                float s0 = 0.5f * (A0.z * dx0 * dx0 + B0.x * dy0 * dy0) + A0.w * dx0 * dy0;
                float s1 = 0.5f * (A1.z * dx1 * dx1 + B1.x * dy1 * dy1) + A1.w * dx1 * dy1;
                float a0 = fminf(B0.y * __expf(-s0), 0.999f);
                float a1 = fminf(B1.y * __expf(-s1), 0.999f);
                a0 = (s0 >= 0.f && s0 <= 5.55f && a0 >= (1.f / 255.f)) ? a0 : 0.f;
                a1 = (s1 >= 0.f && s1 <= 5.55f && a1 >= (1.f / 255.f)) ? a1 : 0.f;
                float2 C0 = cC[j], C1 = cC[j + 1];
                float w0 = a0 * T;
                r_ += w0 * B0.z; g += w0 * B0.w; b += w0 * C0.x;
                accD += w0 * C0.y; accW += w0;
                T *= (1.0f - a0);
                float w1 = a1 * T;
                r_ += w1 * B1.z; g += w1 * B1.w; b += w1 * C1.x;
                accD += w1 * C1.y; accW += w1;
                T *= (1.0f - a1);
            }
            if (j < jend && !(T < 1e-5f)) {
                float4 A0 = cA[j];
                float4 B0 = cB[j];
                float dx0 = px - A0.x, dy0 = py - A0.y;
                float s0 = 0.5f * (A0.z * dx0 * dx0 + B0.x * dy0 * dy0) + A0.w * dx0 * dy0;
                float a0 = fminf(B0.y * __expf(-s0), 0.999f);
                a0 = (s0 >= 0.f && s0 <= 5.55f && a0 >= (1.f / 255.f)) ? a0 : 0.f;
                float2 C0 = cC[j];
                float w0 = a0 * T;
                r_ += w0 * B0.z; g += w0 * B0.w; b += w0 * C0.x;
                accD += w0 * C0.y; accW += w0;
                T *= (1.0f - a0);
            }

            // ---- combine: res = p0 + T0*p1 + T0*T1*p2 + T0*T1*T2*p3 ----
            if (qtr > 0) {
                pA[qtr - 1][pid] = make_float4(r_, g, b, accW);
                pC[qtr - 1][pid] = make_float2(accD, T);
            }
            __syncthreads();
            if (qtr == 0 && inb) {
                float4 P1 = pA[0][pid], P2 = pA[1][pid], P3 = pA[2][pid];
                float2 Q1 = pC[0][pid], Q2 = pC[1][pid], Q3 = pC[2][pid];
                float t01  = T * Q1.y;
                float t012 = t01 * Q2.y;
                r_   += T * P1.x + t01 * P2.x + t012 * P3.x;
                g    += T * P1.y + t01 * P2.y + t012 * P3.y;
                b    += T * P1.z + t01 * P2.z + t012 * P3.z;
                accW += T * P1.w + t01 * P2.w + t012 * P3.w;
                accD += T * Q1.x + t01 * Q2.x + t012 * Q3.x;
                int p = pyI * W + pxI;
                float ed = accD / fmaxf(accW, 1e-10f);
                ((float4*)out)[p] = make_float4(r_, g, b, ed);
                out[pixels * 4 + p] = accW;
            }
            __syncthreads();   // protect smem reuse across grid-stride tiles
        }
    }

    // ================= EXIT / RESET =================
    __syncthreads();
    if (tid == 0) {
        int old = atomicAdd(&g_exit, 1);
        if (old % (int)gridDim.x == (int)gridDim.x - 1) {
            *(volatile int*)&g_done = 0;   // last block out resets for next replay
        }
    }
}

extern "C" void kernel_launch(void* const* d_in, const int* in_sizes, int n_in,
                              void* d_out, int out_size) {
    const float* means3d = (const float*)d_in[0];
    const float* quats   = (const float*)d_in[1];
    const float* scales  = (const float*)d_in[2];
    const float* opac    = (const float*)d_in[3];
    const float* sh      = (const float*)d_in[4];
    const float* c2w     = (const float*)d_in[5];
    const float* Ks      = (const float*)d_in[6];
    const int*   wptr    = (const int*)d_in[7];
    float* out = (float*)d_out;

    int N = in_sizes[0] / 3;
    if (N > NMAX) N = NMAX;
    int pixels = out_size / 5;

    int renderBlocks = (pixels + PIX - 1) / PIX;
    if (renderBlocks < 1) renderBlocks = 1;
    gs_fused_kernel<<<PREB + renderBlocks, RT>>>(means3d, quats, scales, opac, sh,
                                                 c2w, Ks, wptr, out, N, pixels);
}

// round 15
// speedup vs baseline: 7.2423x; 1.2041x over previous
#include <cuda_runtime.h>
#include <math.h>

#define NMAX   1024
#define TW     16
#define TH     8
#define RT     512            // threads per block
#define PIX    128            // pixels per tile
#define ROUNDS (NMAX / RT)    // 2 cull rounds
#define PREB   32             // preprocess blocks (1 math warp each)
#define GPB    (NMAX / PREB)  // 32 gaussians per preprocess block
#define OPCUT  (-5.53f)       // sigmoid(o) > 1/255  <=>  o > -5.5373 (conservative)

static __device__ __forceinline__ float finf() { return __int_as_float(0x7f800000); }

// UNSORTED per-gaussian data (render sorts survivors per tile)
__device__ float4 u_A[NMAX]; // mx, my, conA, conB
__device__ float4 u_B[NMAX]; // conC, op, colR, colG
__device__ float2 u_C[NMAX]; // colB, depth
__device__ float4 u_D[NMAX]; // xmin, xmax, ymin, ymax (empty box => culled)
__device__ float  u_K[NMAX]; // depth key (+inf if culled)
// Cross-block sync
__device__ int g_done = 0;   // # preprocess blocks finished
__device__ int g_exit = 0;   // monotone exit counter (never reset)

__global__ __launch_bounds__(RT, 2) void gs_fused_kernel(
    const float* __restrict__ means3d,   // [N,3]
    const float* __restrict__ quats,     // [N,4]
    const float* __restrict__ scales,    // [N,3]
    const float* __restrict__ opac,      // [N]
    const float* __restrict__ sh,        // [N,4,3]
    const float* __restrict__ c2w,       // [4,4]
    const float* __restrict__ Ks,        // [3,3]
    const int*   __restrict__ wptr,
    float* __restrict__ out,
    int N, int pixels)
{
    __shared__ float4 cA[NMAX];
    __shared__ float4 cB[NMAX];
    __shared__ float2 cC[NMAX];
    __shared__ float  skeys[NMAX];
    __shared__ int    sidx[NMAX];
    __shared__ float4 pA[3][PIX];
    __shared__ float2 pC[3][PIX];
    __shared__ int    warpCnt[ROUNDS * 16];

    const int tid = threadIdx.x;

    if (blockIdx.x < PREB) {
        // ================= PREPROCESS BLOCK (math only, 1 warp) =================
        const int i = blockIdx.x * GPB + tid;
        if (tid < GPB && i < N) {
            const float SH_C0 = 0.28209479177387814f;
            const float SH_C1 = 0.4886025119029199f;
            const float NEARP = 0.01f;
            const float FARP  = 1e10f;
            const float LOWPASS = 0.3f;

            // fire gaussian loads first
            const float4 q4  = *(const float4*)(quats + i * 4);
            const float4 sh0 = *(const float4*)(sh + i * 12);
            const float4 sh1 = *(const float4*)(sh + i * 12 + 4);
            const float4 sh2 = *(const float4*)(sh + i * 12 + 8);
            float m0 = means3d[i * 3 + 0], m1 = means3d[i * 3 + 1], m2 = means3d[i * 3 + 2];
            float s0 = scales[i * 3 + 0], s1 = scales[i * 3 + 1], s2v = scales[i * 3 + 2];
            float opraw = opac[i];

            float Rw[3][3];
            #pragma unroll
            for (int r = 0; r < 3; r++)
                #pragma unroll
                for (int c = 0; c < 3; c++)
                    Rw[r][c] = c2w[c * 4 + r];
            float ct0 = c2w[3], ct1 = c2w[7], ct2 = c2w[11];
            float tw[3];
            #pragma unroll
            for (int r = 0; r < 3; r++)
                tw[r] = -(Rw[r][0] * ct0 + Rw[r][1] * ct1 + Rw[r][2] * ct2);

            float fx = Ks[0], cx = Ks[2], fy = Ks[4], cy = Ks[5];

            float x = Rw[0][0] * m0 + Rw[0][1] * m1 + Rw[0][2] * m2 + tw[0];
            float y = Rw[1][0] * m0 + Rw[1][1] * m1 + Rw[1][2] * m2 + tw[1];
            float z = Rw[2][0] * m0 + Rw[2][1] * m1 + Rw[2][2] * m2 + tw[2];

            bool valid = (z > NEARP) && (z < FARP);
            float zs = valid ? z : 1.0f;
            float izs = 1.0f / zs;
            float m2x = fx * x * izs + cx;
            float m2y = fy * y * izs + cy;

            float qw = q4.x, qx = q4.y, qy = q4.z, qz = q4.w;
            float qn = rsqrtf(qw * qw + qx * qx + qy * qy + qz * qz);
            qw *= qn; qx *= qn; qy *= qn; qz *= qn;
            float Rg[3][3];
            Rg[0][0] = 1.f - 2.f * (qy * qy + qz * qz);
            Rg[0][1] = 2.f * (qx * qy - qw * qz);
            Rg[0][2] = 2.f * (qx * qz + qw * qy);
            Rg[1][0] = 2.f * (qx * qy + qw * qz);
            Rg[1][1] = 1.f - 2.f * (qx * qx + qz * qz);
            Rg[1][2] = 2.f * (qy * qz - qw * qx);
            Rg[2][0] = 2.f * (qx * qz - qw * qy);
            Rg[2][1] = 2.f * (qy * qz + qw * qx);
            Rg[2][2] = 1.f - 2.f * (qx * qx + qy * qy);

            float sq[3] = { s0 * s0, s1 * s1, s2v * s2v };

            float cov3[3][3];
            #pragma unroll
            for (int r = 0; r < 3; r++)
                #pragma unroll
                for (int c = 0; c < 3; c++)
                    cov3[r][c] = Rg[r][0] * Rg[c][0] * sq[0]
                               + Rg[r][1] * Rg[c][1] * sq[1]
                               + Rg[r][2] * Rg[c][2] * sq[2];

            float Vc[3][3];
            #pragma unroll
            for (int r = 0; r < 3; r++)
                #pragma unroll
                for (int c = 0; c < 3; c++)
                    Vc[r][c] = Rw[r][0] * cov3[0][c] + Rw[r][1] * cov3[1][c] + Rw[r][2] * cov3[2][c];
            float cc[3][3];
            #pragma unroll
            for (int r = 0; r < 3; r++)
                #pragma unroll
                for (int c = 0; c < 3; c++)
                    cc[r][c] = Vc[r][0] * Rw[c][0] + Vc[r][1] * Rw[c][1] + Vc[r][2] * Rw[c][2];

            float j00 = fx * izs, j02 = -fx * x * izs * izs;
            float j11 = fy * izs, j12 = -fy * y * izs * izs;
            float a = j00 * (cc[0][0] * j00 + cc[0][2] * j02)
                    + j02 * (cc[2][0] * j00 + cc[2][2] * j02);
            float b = j00 * (cc[0][1] * j11 + cc[0][2] * j12)
                    + j02 * (cc[2][1] * j11 + cc[2][2] * j12);
            float c = j11 * (cc[1][1] * j11 + cc[1][2] * j12)
                    + j12 * (cc[2][1] * j11 + cc[2][2] * j12);
            a += LOWPASS;
            c += LOWPASS;
            float det = a * c - b * b;
            valid = valid && (det > 0.f);
            float dets = (det > 0.f) ? det : 1.0f;
            float idet = 1.0f / dets;
            float conA = c * idet, conB = -b * idet, conC = a * idet;

            float dx3 = m0 - ct0, dy3 = m1 - ct1, dz3 = m2 - ct2;
            float dn = sqrtf(dx3 * dx3 + dy3 * dy3 + dz3 * dz3);
            dn = fmaxf(dn, 1e-8f);
            float idn = 1.0f / dn;
            float dxn = dx3 * idn, dyn = dy3 * idn, dzn = dz3 * idn;
            float shv[12] = { sh0.x, sh0.y, sh0.z, sh0.w, sh1.x, sh1.y, sh1.z, sh1.w,
                              sh2.x, sh2.y, sh2.z, sh2.w };
            float col[3];
            #pragma unroll
            for (int ch = 0; ch < 3; ch++) {
                float v = SH_C0 * shv[ch]
                        - SH_C1 * dyn * shv[3 + ch]
                        + SH_C1 * dzn * shv[6 + ch]
                        - SH_C1 * dxn * shv[9 + ch];
                col[ch] = fmaxf(v + 0.5f, 0.0f);
            }

            float op = 1.0f / (1.0f + __expf(-opraw));
            op = valid ? op : 0.0f;

            float xmin = 1e30f, xmax = -1e30f, ymin = 1e30f, ymax = -1e30f;
            bool lit = valid && (opraw > OPCUT);
            if (lit) {
                float sg = fminf(5.55f, logf(255.f * op));
                float rx = sqrtf(2.f * sg * a);
                float ry = sqrtf(2.f * sg * c);
                xmin = m2x - rx; xmax = m2x + rx;
                ymin = m2y - ry; ymax = m2y + ry;
            } else {
                op = 0.f;
            }

            u_A[i] = make_float4(m2x, m2y, conA, conB);
            u_B[i] = make_float4(conC, op, col[0], col[1]);
            u_C[i] = make_float2(col[2], z);
            u_D[i] = make_float4(xmin, xmax, ymin, ymax);
            u_K[i] = lit ? z : finf();
        }
        __threadfence();
        __syncthreads();
        if (tid == 0) atomicAdd(&g_done, 1);
    } else {
        // ================= RENDER BLOCK =================
        if (tid == 0) {
            while (*(volatile int*)&g_done < PREB) __nanosleep(64);
        }
        __syncthreads();
        __threadfence();

        const int warp = tid >> 5;
        const int lane = tid & 31;
        const unsigned lanemask = (1u << lane) - 1u;
        const int pid  = tid & (PIX - 1);
        const int qtr  = tid >> 7;

        const int W = *wptr;
        const int H = pixels / W;
        const int tilesX = (W + TW - 1) / TW;
        const int tilesY = (H + TH - 1) / TH;
        const int tileCount = tilesX * tilesY;
        const int rstride = gridDim.x - PREB;

        for (int t = blockIdx.x - PREB; t < tileCount; t += rstride) {
            int tx = t % tilesX;
            int ty = t / tilesX;
            int x0 = tx * TW;
            int y0 = ty * TH;

            int pxI = x0 + (pid & (TW - 1));
            int pyI = y0 + (pid / TW);
            bool inb = (pxI < W) && (pyI < H);
            float px = (float)pxI + 0.5f;
            float py = (float)pyI + 0.5f;

            float xlo = (float)x0, xhi = (float)(x0 + TW);
            float ylo = (float)y0, yhi = (float)(y0 + TH);

            // ---- cull: 2 ballot rounds, record (key, gidx) of survivors ----
            unsigned ball[ROUNDS];
            unsigned predMask = 0;
            #pragma unroll
            for (int r = 0; r < ROUNDS; r++) {
                int gi = r * RT + tid;
                bool pred = false;
                if (gi < N) {
                    float4 D = u_D[gi];
                    pred = (D.y >= xlo) && (D.x <= xhi) && (D.w >= ylo) && (D.z <= yhi);
                }
                ball[r] = __ballot_sync(0xffffffffu, pred);
                predMask |= pred ? (1u << r) : 0u;
                if (lane == 0) warpCnt[r * 16 + warp] = __popc(ball[r]);
            }
            __syncthreads();

            int wb[ROUNDS];
            int rb = 0;
            #pragma unroll
            for (int r = 0; r < ROUNDS; r++) {
                int wbase = rb;
                #pragma unroll
                for (int w2 = 0; w2 < 16; w2++) {
                    int cw = warpCnt[r * 16 + w2];
                    if (w2 < warp) wbase += cw;
                    rb += cw;
                }
                wb[r] = wbase;
            }
            const int total = rb;

            #pragma unroll
            for (int r = 0; r < ROUNDS; r++) {
                if (predMask & (1u << r)) {
                    int gi = r * RT + tid;
                    int off = wb[r] + __popc(ball[r] & lanemask);
                    skeys[off] = u_K[gi];
                    sidx[off]  = gi;
                }
            }
            __syncthreads();

            // ---- stable rank-sort survivors by (key, gidx); gather sorted ----
            for (int s = tid; s < total; s += RT) {
                float ki = skeys[s];
                int   gi = sidx[s];
                int rank = 0;
                #pragma unroll 4
                for (int j = 0; j < total; j++) {
                    float kj = skeys[j];
                    rank += (kj < ki) || ((kj == ki) && (sidx[j] < gi));
                }
                cA[rank] = u_A[gi];
                cB[rank] = u_B[gi];
                cC[rank] = u_C[gi];
            }
            __syncthreads();

            // ---- composite: 4-way split-T, branchless, 2x unrolled ----
            const int s = (total + 3) >> 2;
            int jbeg = qtr * s;  if (jbeg > total) jbeg = total;
            int jend = jbeg + s; if (jend > total) jend = total;

            float T = 1.0f;
            float r_ = 0.f, g = 0.f, b = 0.f, accW = 0.f, accD = 0.f;

            int j = jbeg;
            for (; j + 1 < jend; j += 2) {
                if (__all_sync(0xffffffffu, T < 1e-5f)) break;
                float4 A0 = cA[j],     A1 = cA[j + 1];
                float4 B0 = cB[j],     B1 = cB[j + 1];
                float dx0 = px - A0.x, dy0 = py - A0.y;
                float dx1 = px - A1.x, dy1 = py - A1.y;
                float s0 = 0.5f * (A0.z * dx0 * dx0 + B0.x * dy0 * dy0) + A0.w * dx0 * dy0;
                float s1 = 0.5f * (A1.z * dx1 * dx1 + B1.x * dy1 * dy1) + A1.w * dx1 * dy1;
                float a0 = fminf(B0.y * __expf(-s0), 0.999f);
                float a1 = fminf(B1.y * __expf(-s1), 0.999f);
                a0 = (s0 >= 0.f && s0 <= 5.55f && a0 >= (1.f / 255.f)) ? a0 : 0.f;
                a1 = (s1 >= 0.f && s1 <= 5.55f && a1 >= (1.f / 255.f)) ? a1 : 0.f;
                float2 C0 = cC[j], C1 = cC[j + 1];
                float w0 = a0 * T;
                r_ += w0 * B0.z; g += w0 * B0.w; b += w0 * C0.x;
                accD += w0 * C0.y; accW += w0;
                T *= (1.0f - a0);
                float w1 = a1 * T;
                r_ += w1 * B1.z; g += w1 * B1.w; b += w1 * C1.x;
                accD += w1 * C1.y; accW += w1;
                T *= (1.0f - a1);
            }
            if (j < jend && !(T < 1e-5f)) {
                float4 A0 = cA[j];
                float4 B0 = cB[j];
                float dx0 = px - A0.x, dy0 = py - A0.y;
                float s0 = 0.5f * (A0.z * dx0 * dx0 + B0.x * dy0 * dy0) + A0.w * dx0 * dy0;
                float a0 = fminf(B0.y * __expf(-s0), 0.999f);
                a0 = (s0 >= 0.f && s0 <= 5.55f && a0 >= (1.f / 255.f)) ? a0 : 0.f;
                float2 C0 = cC[j];
                float w0 = a0 * T;
                r_ += w0 * B0.z; g += w0 * B0.w; b += w0 * C0.x;
                accD += w0 * C0.y; accW += w0;
                T *= (1.0f - a0);
            }

            // ---- combine: res = p0 + T0*p1 + T0*T1*p2 + T0*T1*T2*p3 ----
            if (qtr > 0) {
                pA[qtr - 1][pid] = make_float4(r_, g, b, accW);
                pC[qtr - 1][pid] = make_float2(accD, T);
            }
            __syncthreads();
            if (qtr == 0 && inb) {
                float4 P1 = pA[0][pid], P2 = pA[1][pid], P3 = pA[2][pid];
                float2 Q1 = pC[0][pid], Q2 = pC[1][pid], Q3 = pC[2][pid];
                float t01  = T * Q1.y;
                float t012 = t01 * Q2.y;
                r_   += T * P1.x + t01 * P2.x + t012 * P3.x;
                g    += T * P1.y + t01 * P2.y + t012 * P3.y;
                b    += T * P1.z + t01 * P2.z + t012 * P3.z;
                accW += T * P1.w + t01 * P2.w + t012 * P3.w;
                accD += T * Q1.x + t01 * Q2.x + t012 * Q3.x;
                int p = pyI * W + pxI;
                float ed = accD / fmaxf(accW, 1e-10f);
                ((float4*)out)[p] = make_float4(r_, g, b, ed);
                out[pixels * 4 + p] = accW;
            }
            __syncthreads();   // protect smem reuse across grid-stride tiles
        }
    }

    // ================= EXIT / RESET =================
    __syncthreads();
    if (tid == 0) {
        int old = atomicAdd(&g_exit, 1);
        if (old % (int)gridDim.x == (int)gridDim.x - 1) {
            *(volatile int*)&g_done = 0;   // last block out resets for next replay
        }
    }
}

extern "C" void kernel_launch(void* const* d_in, const int* in_sizes, int n_in,
                              void* d_out, int out_size) {
    const float* means3d = (const float*)d_in[0];
    const float* quats   = (const float*)d_in[1];
    const float* scales  = (const float*)d_in[2];
    const float* opac    = (const float*)d_in[3];
    const float* sh      = (const float*)d_in[4];
    const float* c2w     = (const float*)d_in[5];
    const float* Ks      = (const float*)d_in[6];
    const int*   wptr    = (const int*)d_in[7];
    float* out = (float*)d_out;

    int N = in_sizes[0] / 3;
    if (N > NMAX) N = NMAX;
    int pixels = out_size / 5;

    int renderBlocks = (pixels + PIX - 1) / PIX;
    if (renderBlocks < 1) renderBlocks = 1;
    gs_fused_kernel<<<PREB + renderBlocks, RT>>>(means3d, quats, scales, opac, sh,
                                                 c2w, Ks, wptr, out, N, pixels);
}